// round 12
// baseline (speedup 1.0000x reference)
#include <cuda_runtime.h>
#include <math.h>

typedef unsigned long long ull;

// Problem constants
static constexpr int BN = 4;            // batch
static constexpr int NC = 21;           // classes
static constexpr int H  = 512;
static constexpr int W  = 512;
static constexpr int P  = 171;          // pooled H/W
static constexpr int NH = 169;          // cropped size P - (radius-1)
static constexpr int NPROB = BN * NC;   // 84
static constexpr int MM = NH * NH;      // 28561
static constexpr double D_ALPHA = 5e-4;
static constexpr float  CLIP_MIN = 1e-6f;
static constexpr int SPITCH = 172;      // smem pitch (floats, mult of 4)
static constexpr int SH = 16;           // strip height for k_cov
static constexpr int NSTRIP = (NH + SH - 1) / SH;  // 11
static constexpr int NBLK = P * BN;     // 684 pool blocks

// Scratch (static device globals: no allocation allowed)
__device__ float  g_la[NPROB * P * P];      // pooled one-hot labels
__device__ float  g_pr[NPROB * P * P];      // pooled probs
__device__ double g_S[NPROB * 18 * 18];     // raw second-moment Gram
__device__ double g_sums[NPROB * 18];       // raw first moments
__device__ float2 g_part[NBLK];             // per-block (bce, valid) - plain stores
__device__ double g_rmi[NPROB];
__device__ unsigned int g_ctr;              // last-block ticket (self-resetting)

// stream-pair-block map: 6 lower-tri pairs of the 3 stream-groups
__constant__ int c_PBI[6] = {0, 1, 1, 2, 2, 2};
__constant__ int c_PBJ[6] = {0, 0, 1, 0, 1, 2};

// ---------------------------------------------------------------------------
// Fused: BCE partials + sigmoid + one-hot + 3x3/s3/p1 maxpool. Also zeroes
// the g_S/g_sums slices consumed by later kernels (684 x 42 covers exactly).
// MUFU diet: sum of 9 softplus logs batched as ONE log of the product of
// (1+e^-|x|) terms (each in (1,2], product <= 512 -> exact range, safe).
__global__ void __launch_bounds__(192) k_pool_bce(const float* __restrict__ logits,
                                                  const int*   __restrict__ labels) {
    int py = blockIdx.x;        // 0..170
    int n  = blockIdx.y;        // 0..3
    int tid = threadIdx.x;
    int bid = n * P + py;

    // zero scratch consumed by k_cov (684 blocks x 42 = 28728 doubles exact)
    if (tid < 42) {
        int zi = bid * 42 + tid;
        if (zi < NPROB * 324) g_S[zi] = 0.0;
        else                  g_sums[zi - NPROB * 324] = 0.0;
    }

    __shared__ __align__(16) float slog[3][520];   // data at idx 4..515
    __shared__ float smk[3][520];
    __shared__ int   slab[3][520];
    __shared__ float warp_b[6], warp_v[6];

    int y0 = py * 3 - 1;
    const int* lb = labels + (long)n * H * W;

    for (int i = tid; i < 3 * 520; i += 192) {
        int r = i / 520, x = i - r * 520;
        int xx = x - 4;
        int y  = y0 + r;
        bool v = ((unsigned)y < (unsigned)H) && ((unsigned)xx < (unsigned)W);
        int  l = v ? lb[y * W + xx] : NC;
        slab[r][x] = l;
        smk[r][x]  = (l < NC) ? 1.f : 0.f;
    }
    if (tid < 24) {
        int r = tid / 8, j = tid - r * 8;
        int x = (j < 4) ? j : 512 + j;
        slog[r][x] = 0.f;
    }
    __syncthreads();

    int  px  = tid;
    bool act = px < P;
    float mk[9]; int lab[9];
    float valid_part = 0.f, bce_part = 0.f;
    if (act) {
#pragma unroll
        for (int k = 0; k < 9; k++) {
            int r = k / 3, dx = k % 3;
            int idx = 3 * px + 3 + dx;
            mk[k]  = smk[r][idx];
            lab[k] = slab[r][idx];
            valid_part += mk[k];
        }
    }
    bool rv[3];
#pragma unroll
    for (int r = 0; r < 3; r++) rv[r] = (unsigned)(y0 + r) < (unsigned)H;

    long ppp = (long)P * P;
    for (int c = 0; c < NC; c++) {
        __syncthreads();
        const float* lg = logits + (long)(n * NC + c) * H * W;
        for (int i = tid; i < 384; i += 192) {
            int r = i >> 7, j = i & 127;
            float4 v = make_float4(0.f, 0.f, 0.f, 0.f);
            if (rv[r]) v = ((const float4*)(lg + (long)(y0 + r) * W))[j];
            *(float4*)(&slog[r][4 + 4 * j]) = v;
        }
        __syncthreads();
        if (act) {
            float mla = 0.f, mv = -1e30f;
            float lin = 0.f, prod = 1.f;
#pragma unroll
            for (int k = 0; k < 9; k++) {
                int r = k / 3, dx = k % 3;
                float xv = slog[r][3 * px + 3 + dx];
                float m  = mk[k];
                float t1 = (lab[k] == c) ? m : 0.f;
                lin = fmaf(fmaxf(xv, 0.f), m, lin);
                lin = fmaf(-xv, t1, lin);
                float e = __expf(-fabsf(xv));
                prod *= (m > 0.f) ? (1.f + e) : 1.f;   // batch the 9 logs
                mla = fmaxf(mla, t1);
                mv  = fmaxf(mv, (m > 0.f) ? xv : -1e30f);
            }
            bce_part += lin + __logf(prod);            // ONE log per window
            float em  = __expf(-fabsf(mv));
            float rc  = __fdividef(1.f, 1.f + em);
            float sig = (mv >= 0.f) ? rc : em * rc;    // mv=-1e30 -> 0
            long o = (long)(n * NC + c) * ppp + (long)py * P + px;
            g_la[o] = mla;
            g_pr[o] = sig + CLIP_MIN;
        }
    }

#pragma unroll
    for (int off = 16; off > 0; off >>= 1) {
        bce_part   += __shfl_down_sync(0xffffffffu, bce_part,   off);
        valid_part += __shfl_down_sync(0xffffffffu, valid_part, off);
    }
    int wid = tid >> 5, lane = tid & 31;
    if (lane == 0) { warp_b[wid] = bce_part; warp_v[wid] = valid_part; }
    __syncthreads();
    if (tid == 0) {
        float b = 0.f, v = 0.f;
#pragma unroll
        for (int w = 0; w < 6; w++) { b += warp_b[w]; v += warp_v[w]; }
        g_part[bid] = make_float2(b, v);   // plain store, no init needed
    }
}

// ---------------------------------------------------------------------------
// f32x2 helpers
__device__ __forceinline__ ull pk2(float lo, float hi) {
    ull r; asm("mov.b64 %0, {%1, %2};" : "=l"(r) : "f"(lo), "f"(hi)); return r;
}
#define FMA2(d, a, b) asm("fma.rn.f32x2 %0, %1, %2, %0;" : "+l"(d) : "l"(a), "l"(b))

// One step: acc[j*9+l*3+m] += PA[l-pos] * dup(Bj[m-pos])
#define DOSTEP(PL0, PL1, PL2, B00, B01, B02, B10, B11, B12) do {              \
    ull d00 = pk2((B00),(B00)), d01 = pk2((B01),(B01)), d02 = pk2((B02),(B02)); \
    ull d10 = pk2((B10),(B10)), d11 = pk2((B11),(B11)), d12 = pk2((B12),(B12)); \
    FMA2(acc[0],  PL0, d00); FMA2(acc[1],  PL0, d01); FMA2(acc[2],  PL0, d02); \
    FMA2(acc[3],  PL1, d00); FMA2(acc[4],  PL1, d01); FMA2(acc[5],  PL1, d02); \
    FMA2(acc[6],  PL2, d00); FMA2(acc[7],  PL2, d01); FMA2(acc[8],  PL2, d02); \
    FMA2(acc[9],  PL0, d10); FMA2(acc[10], PL0, d11); FMA2(acc[11], PL0, d12); \
    FMA2(acc[12], PL1, d10); FMA2(acc[13], PL1, d11); FMA2(acc[14], PL1, d12); \
    FMA2(acc[15], PL2, d10); FMA2(acc[16], PL2, d11); FMA2(acc[17], PL2, d12); \
} while (0)

#define PAW(t) ((t) < 4 ? PA[(t)]  : PAn[(t) - 4])
#define B0W(t) ((t) < 4 ? b0c[(t)] : b0n[(t) - 4])
#define B1W(t) ((t) < 4 ? b1c[(t)] : b1n[(t) - 4])

// Gram matrix of the 18 shifted views via 6 stream-pair-blocks; also folds in
// the per-view first-moment sums (row-total minus edges trick).
__global__ void __launch_bounds__(96, 6) k_cov() {
    int p     = blockIdx.x;
    int strip = blockIdx.y;
    int ys = strip * SH;
    int sh = min(SH, NH - ys);

    __shared__ __align__(16) float sbuf[2 * 18 * SPITCH];  // la rows | pr rows
    __shared__ float srs[36];
    float* sla = sbuf;
    float* spr = sbuf + 18 * SPITCH;

    int tid = threadIdx.x;
    int row = tid & 15;
    int pb  = tid >> 4;
    const float* la = g_la + p * P * P;
    const float* pr = g_pr + p * P * P;

    int nrows = sh + 2;
    for (int i = tid; i < nrows * P; i += 96) {
        int r = i / P, x = i - r * P;
        sla[r * SPITCH + x] = la[(ys + r) * P + x];
        spr[r * SPITCH + x] = pr[(ys + r) * P + x];
    }
    __syncthreads();

    ull acc[18];
#pragma unroll
    for (int k = 0; k < 18; k++) acc[k] = 0ULL;

    if (row < sh) {
        int gi = c_PBI[pb], gj = c_PBJ[pb];
        int sA0 = 2 * gi, sA1 = 2 * gi + 1, sB0 = 2 * gj, sB1 = 2 * gj + 1;
        const float* pA0 = ((sA0 < 3) ? sla : spr) + ((sA0 < 3 ? sA0 : sA0 - 3) + row) * SPITCH;
        const float* pA1 = ((sA1 < 3) ? sla : spr) + ((sA1 < 3 ? sA1 : sA1 - 3) + row) * SPITCH;
        const float* pB0 = ((sB0 < 3) ? sla : spr) + ((sB0 < 3 ? sB0 : sB0 - 3) + row) * SPITCH;
        const float* pB1 = ((sB1 < 3) ? sla : spr) + ((sB1 < 3 ? sB1 : sB1 - 3) + row) * SPITCH;

        float4 va = *(const float4*)(pA0);
        float4 vb = *(const float4*)(pA1);
        ull PA[4] = { pk2(va.x, vb.x), pk2(va.y, vb.y), pk2(va.z, vb.z), pk2(va.w, vb.w) };
        float4 v0 = *(const float4*)(pB0);
        float4 v1 = *(const float4*)(pB1);
        float b0c[4] = { v0.x, v0.y, v0.z, v0.w };
        float b1c[4] = { v1.x, v1.y, v1.z, v1.w };

        for (int x = 0; x + 4 <= NH - 1; x += 4) {   // steps 0..167
            va = *(const float4*)(pA0 + x + 4);
            vb = *(const float4*)(pA1 + x + 4);
            ull PAn[4] = { pk2(va.x, vb.x), pk2(va.y, vb.y), pk2(va.z, vb.z), pk2(va.w, vb.w) };
            v0 = *(const float4*)(pB0 + x + 4);
            v1 = *(const float4*)(pB1 + x + 4);
            float b0n[4] = { v0.x, v0.y, v0.z, v0.w };
            float b1n[4] = { v1.x, v1.y, v1.z, v1.w };
#pragma unroll
            for (int s = 0; s < 4; s++)
                DOSTEP(PAW(s), PAW(s + 1), PAW(s + 2),
                       B0W(s), B0W(s + 1), B0W(s + 2),
                       B1W(s), B1W(s + 1), B1W(s + 2));
#pragma unroll
            for (int t = 0; t < 4; t++) { PA[t] = PAn[t]; b0c[t] = b0n[t]; b1c[t] = b1n[t]; }
        }
        // tail step x = 168 (positions 168..170)
        DOSTEP(PA[0], PA[1], PA[2], b0c[0], b0c[1], b0c[2], b1c[0], b1c[1], b1c[2]);
    }

    // ---- folded first-moment sums (row totals minus edge elements) ----
    if (tid < 36) {
        int mp = tid / 18, r = tid % 18;
        float T = 0.f;
        if (r < sh + 2) {
            const float* rowp = (mp ? spr : sla) + r * SPITCH;
            for (int x = 0; x < P; x++) T += rowp[x];
        }
        srs[tid] = T;
    }
    __syncthreads();
    if (tid < 18) {
        int mp = tid / 9, dd = tid % 9, dy = dd / 3, dx = dd % 3;
        const float* base = mp ? spr : sla;
        float part = 0.f;
        for (int yl = 0; yl < sh; yl++) {
            int r = yl + dy;
            const float* rowp = base + r * SPITCH;
            float T = srs[mp * 18 + r];
            float rs = (dx == 0) ? T - rowp[169] - rowp[170]
                     : (dx == 1) ? T - rowp[0]   - rowp[170]
                     :             T - rowp[0]   - rowp[1];
            part += rs;
        }
        atomicAdd(&g_sums[p * 18 + tid], (double)part);
    }
    __syncthreads();

    // ---- reduce 96x36 partials over the 16 rows, flush to g_S ----
    float* red = sbuf;             // overlay (96*36 floats)
#pragma unroll
    for (int k = 0; k < 18; k++) {
        float lo, hi;
        asm("mov.b64 {%0, %1}, %2;" : "=f"(lo), "=f"(hi) : "l"(acc[k]));
        red[tid * 36 + k]      = lo;   // i = 0 (stream 2gi)
        red[tid * 36 + 18 + k] = hi;   // i = 1 (stream 2gi+1)
    }
    __syncthreads();
    for (int o = tid; o < 216; o += 96) {
        int pb2 = o / 36, q = o % 36;
        float ssum = 0.f;
#pragma unroll
        for (int r2 = 0; r2 < 16; r2++) ssum += red[(pb2 * 16 + r2) * 36 + q];
        int i = q / 18, k = q % 18;
        int j = k / 9, l = (k % 9) / 3, m = k % 3;
        int a = (2 * c_PBI[pb2] + i) * 3 + l;
        int b = (2 * c_PBJ[pb2] + j) * 3 + m;
        atomicAdd(&g_S[p * 324 + a * 18 + b], (double)ssum);
    }
}

// ---------------------------------------------------------------------------
// Warp-parallel 9x9 Cholesky (fp32; matrices are well-conditioned)
__device__ __forceinline__ void chol9f(float* A, int lane) {
    for (int k = 0; k < 9; k++) {
        if (lane == 0) A[k * 9 + k] = sqrtf(A[k * 9 + k]);
        __syncwarp();
        float rd = __fdividef(1.f, A[k * 9 + k]);
        if (lane > k && lane < 9) A[lane * 9 + k] *= rd;
        __syncwarp();
        for (int idx = lane; idx < 81; idx += 32) {
            int i = idx / 9, j = idx % 9;
            if (j > k && j <= i) A[i * 9 + j] -= A[i * 9 + k] * A[j * 9 + k];
        }
        __syncwarp();
    }
}

// One warp per (n,c): assemble covariances in double, solve in float (proven
// path). Last-finishing block also does the final reduction (proven in R6).
__global__ void __launch_bounds__(32) k_solve(float* __restrict__ out) {
    int p    = blockIdx.x;
    int lane = threadIdx.x;
    __shared__ float A[81], B[81], C2[81], V[81];
    __shared__ unsigned int ticket;
    const double* S  = g_S    + p * 324;
    const double* sm = g_sums + p * 18;
    const double invM = 1.0 / (double)MM;
    for (int idx = lane; idx < 81; idx += 32) {
        int i = idx / 9, j = idx % 9;
        int a = 9 + i, b = 9 + j;
        int hi = a > b ? a : b, lo = a > b ? b : a;
        A[idx] = (float)(S[hi * 18 + lo] - sm[a] * sm[b] * invM + (i == j ? D_ALPHA : 0.0));
        B[idx] = (float)(S[(9 + j) * 18 + i] - sm[i] * sm[9 + j] * invM);   // cross[d][e]
        hi = i > j ? i : j; lo = i > j ? j : i;
        C2[idx] = (float)(S[hi * 18 + lo] - sm[i] * sm[j] * invM);          // la_cov
    }
    __syncwarp();
    chol9f(A, lane);
    if (lane < 9) {   // forward solve L V = cross^T (column d per lane)
        int d = lane;
        for (int e = 0; e < 9; e++) {
            float t = B[d * 9 + e];
            for (int j = 0; j < e; j++) t -= A[e * 9 + j] * V[j * 9 + d];
            V[e * 9 + d] = t * __fdividef(1.f, A[e * 9 + e]);
        }
    }
    __syncwarp();
    for (int idx = lane; idx < 81; idx += 32) {   // appro_var = la_cov - V^T V + aI
        int i = idx / 9, j = idx % 9;
        float t = C2[idx];
#pragma unroll
        for (int k = 0; k < 9; k++) t -= V[k * 9 + i] * V[k * 9 + j];
        if (i == j) t += (float)D_ALPHA;
        B[idx] = t;
    }
    __syncwarp();
    chol9f(B, lane);
    float lsum = (lane < 9) ? logf(B[lane * 9 + lane]) : 0.f;   // 0.5*logdet
    for (int off = 16; off > 0; off >>= 1)
        lsum += __shfl_down_sync(0xffffffffu, lsum, off);
    if (lane == 0) g_rmi[p] = (double)lsum;

    // ---- last-block final reduction (threadFenceReduction pattern) ----
    __threadfence();
    if (lane == 0) ticket = atomicAdd(&g_ctr, 1u);
    __syncwarp();
    if (ticket == NPROB - 1) {
        double rs = 0.0, bs = 0.0, vs = 0.0;
        for (int i = lane; i < NPROB; i += 32) rs += __ldcg(&g_rmi[i]);
        for (int i = lane; i < NBLK; i += 32) {
            float2 pv = __ldcg(&g_part[i]);
            bs += (double)pv.x; vs += (double)pv.y;
        }
#pragma unroll
        for (int off = 16; off > 0; off >>= 1) {
            rs += __shfl_down_sync(0xffffffffu, rs, off);
            bs += __shfl_down_sync(0xffffffffu, bs, off);
            vs += __shfl_down_sync(0xffffffffu, vs, off);
        }
        if (lane == 0) {
            double rmi = rs / 36.0;                 // mean over batch(4)/half_d(9)
            double bce = bs / (vs + 1.0);
            out[0] = (float)(0.5 * bce + 0.5 * rmi);
            g_ctr = 0;                              // reset for next graph replay
        }
    }
}

// ---------------------------------------------------------------------------
extern "C" void kernel_launch(void* const* d_in, const int* in_sizes, int n_in,
                              void* d_out, int out_size) {
    const float* logits = (const float*)d_in[0];
    const int*   labels = (const int*)d_in[1];
    float* out = (float*)d_out;

    k_pool_bce<<<dim3(P, BN), 192>>>(logits, labels);
    k_cov<<<dim3(NPROB, NSTRIP), 96>>>();
    k_solve<<<NPROB, 32>>>(out);
}

// round 13
// speedup vs baseline: 1.0028x; 1.0028x over previous
#include <cuda_runtime.h>
#include <math.h>

typedef unsigned long long ull;

// Problem constants
static constexpr int BN = 4;            // batch
static constexpr int NC = 21;           // classes
static constexpr int H  = 512;
static constexpr int W  = 512;
static constexpr int P  = 171;          // pooled H/W
static constexpr int NH = 169;          // cropped size P - (radius-1)
static constexpr int NPROB = BN * NC;   // 84
static constexpr int MM = NH * NH;      // 28561
static constexpr double D_ALPHA = 5e-4;
static constexpr float  CLIP_MIN = 1e-6f;
static constexpr int SPITCH = 172;      // smem pitch (floats, mult of 4)
static constexpr int SH = 16;           // strip height for k_cov
static constexpr int NSTRIP = (NH + SH - 1) / SH;  // 11
static constexpr int NBLK = P * BN;     // 684 pool blocks

// Scratch (static device globals: no allocation allowed)
__device__ float  g_la[NPROB * P * P];      // pooled one-hot labels
__device__ float  g_pr[NPROB * P * P];      // pooled probs
__device__ double g_S[NPROB * 18 * 18];     // raw second-moment Gram
__device__ double g_sums[NPROB * 18];       // raw first moments
__device__ float2 g_part[NBLK];             // per-block (bce, valid) - plain stores
__device__ double g_rmi[NPROB];
__device__ unsigned int g_ctr;              // last-block ticket (self-resetting)

// stream-pair-block map: 6 lower-tri pairs of the 3 stream-groups
__constant__ int c_PBI[6] = {0, 1, 1, 2, 2, 2};
__constant__ int c_PBJ[6] = {0, 0, 1, 0, 1, 2};

// ---------------------------------------------------------------------------
// Fused: BCE partials + sigmoid + one-hot + 3x3/s3/p1 maxpool. Also zeroes
// the g_S/g_sums slices consumed by later kernels.
// NEW: software-pipelined double buffering — class c+1's LDGs issue before
// computing class c from smem; STS after compute; ONE sync per class. The
// ~577cyc DRAM latency hides under compute instead of serializing 21x.
__global__ void __launch_bounds__(192) k_pool_bce(const float* __restrict__ logits,
                                                  const int*   __restrict__ labels) {
    int py = blockIdx.x;        // 0..170
    int n  = blockIdx.y;        // 0..3
    int tid = threadIdx.x;
    int bid = n * P + py;

    // zero scratch consumed by k_cov (684 blocks x 42 = 28728 doubles exact)
    if (tid < 42) {
        int zi = bid * 42 + tid;
        if (zi < NPROB * 324) g_S[zi] = 0.0;
        else                  g_sums[zi - NPROB * 324] = 0.0;
    }

    __shared__ __align__(16) float slog[2][3][520];   // double-buffered, data at 4..515
    __shared__ int   slab[3][520];
    __shared__ float warp_b[6], warp_v[6];

    int y0 = py * 3 - 1;
    const int* lb = labels + (long)n * H * W;

    // stage labels (pads get l=NC -> mask 0)
    for (int i = tid; i < 3 * 520; i += 192) {
        int r = i / 520, x = i - r * 520;
        int xx = x - 4;
        int y  = y0 + r;
        bool v = ((unsigned)y < (unsigned)H) && ((unsigned)xx < (unsigned)W);
        slab[r][x] = v ? lb[y * W + xx] : NC;
    }
    // zero pad columns of BOTH logit buffers (never overwritten by staging)
    if (tid < 48) {
        int b = tid / 24, rem = tid - b * 24;
        int r = rem / 8, j = rem - r * 8;
        int x = (j < 4) ? j : 512 + j;
        slog[b][r][x] = 0.f;
    }

    // fixed per-thread staging slots: i0 = tid, i1 = tid + 192
    int r0 = tid >> 7,        j0 = tid & 127;          // r0 in {0,1}
    int r1 = (tid + 192) >> 7, j1 = (tid + 192) & 127; // r1 in {1,2}
    bool v0ok = (unsigned)(y0 + r0) < (unsigned)H;
    bool v1ok = (unsigned)(y0 + r1) < (unsigned)H;
    const long HW = (long)H * W;
    const float4* p0 = (const float4*)(logits + (long)(n * NC) * HW + (long)(y0 + r0) * W) + j0;
    const float4* p1 = (const float4*)(logits + (long)(n * NC) * HW + (long)(y0 + r1) * W) + j1;
    const long HW4 = HW / 4;

    // preload + store class 0
    {
        float4 a = make_float4(0.f, 0.f, 0.f, 0.f), b = a;
        if (v0ok) a = *p0;
        if (v1ok) b = *p1;
        p0 += HW4; p1 += HW4;
        *(float4*)&slog[0][r0][4 + 4 * j0] = a;
        *(float4*)&slog[0][r1][4 + 4 * j1] = b;
    }
    __syncthreads();

    int  px  = tid;
    bool act = px < P;
    int  xb  = 3 * px + 3;
    float mk[9]; int lab[9];
    float valid_part = 0.f, bce_part = 0.f;
    if (act) {
#pragma unroll
        for (int k = 0; k < 9; k++) {
            int r = k / 3, dx = k % 3;
            int l = slab[r][xb + dx];
            lab[k] = l;
            mk[k]  = (l < NC) ? 1.f : 0.f;
            valid_part += mk[k];
        }
    }

    const long PPP = (long)P * P;
    float* pla = g_la + (long)(n * NC) * PPP + (long)py * P + px;
    float* ppr = g_pr + (long)(n * NC) * PPP + (long)py * P + px;

    for (int c = 0; c < NC; c++) {
        // issue next class's loads early (latency hidden under compute)
        float4 na = make_float4(0.f, 0.f, 0.f, 0.f), nb = na;
        if (c + 1 < NC) {
            if (v0ok) na = *p0;
            if (v1ok) nb = *p1;
            p0 += HW4; p1 += HW4;
        }
        if (act) {
            const float* sl = &slog[c & 1][0][0];
            float mla = 0.f, mv = -1e30f;
            float lin = 0.f, prod = 1.f;
#pragma unroll
            for (int k = 0; k < 9; k++) {
                int r = k / 3, dx = k % 3;
                float xv = sl[r * 520 + xb + dx];
                float m  = mk[k];
                float t1 = (lab[k] == c) ? m : 0.f;
                lin = fmaf(fmaxf(xv, 0.f), m, lin);
                lin = fmaf(-xv, t1, lin);
                float e = __expf(-fabsf(xv));
                prod *= (m > 0.f) ? (1.f + e) : 1.f;   // batch the 9 logs
                mla = fmaxf(mla, t1);
                mv  = fmaxf(mv, (m > 0.f) ? xv : -1e30f);
            }
            bce_part += lin + __logf(prod);            // ONE log per window
            float em  = __expf(-fabsf(mv));
            float rc  = __fdividef(1.f, 1.f + em);
            float sig = (mv >= 0.f) ? rc : em * rc;    // mv=-1e30 -> 0
            *pla = mla;
            *ppr = sig + CLIP_MIN;
        }
        pla += PPP; ppr += PPP;
        if (c + 1 < NC) {   // STS waits on LDG here, after compute
            *(float4*)&slog[(c + 1) & 1][r0][4 + 4 * j0] = na;
            *(float4*)&slog[(c + 1) & 1][r1][4 + 4 * j1] = nb;
        }
        __syncthreads();
    }

#pragma unroll
    for (int off = 16; off > 0; off >>= 1) {
        bce_part   += __shfl_down_sync(0xffffffffu, bce_part,   off);
        valid_part += __shfl_down_sync(0xffffffffu, valid_part, off);
    }
    int wid = tid >> 5, lane = tid & 31;
    if (lane == 0) { warp_b[wid] = bce_part; warp_v[wid] = valid_part; }
    __syncthreads();
    if (tid == 0) {
        float b = 0.f, v = 0.f;
#pragma unroll
        for (int w = 0; w < 6; w++) { b += warp_b[w]; v += warp_v[w]; }
        g_part[bid] = make_float2(b, v);   // plain store, no init needed
    }
}

// ---------------------------------------------------------------------------
// f32x2 helpers
__device__ __forceinline__ ull pk2(float lo, float hi) {
    ull r; asm("mov.b64 %0, {%1, %2};" : "=l"(r) : "f"(lo), "f"(hi)); return r;
}
#define FMA2(d, a, b) asm("fma.rn.f32x2 %0, %1, %2, %0;" : "+l"(d) : "l"(a), "l"(b))

// One step: acc[j*9+l*3+m] += PA[l-pos] * dup(Bj[m-pos])
#define DOSTEP(PL0, PL1, PL2, B00, B01, B02, B10, B11, B12) do {              \
    ull d00 = pk2((B00),(B00)), d01 = pk2((B01),(B01)), d02 = pk2((B02),(B02)); \
    ull d10 = pk2((B10),(B10)), d11 = pk2((B11),(B11)), d12 = pk2((B12),(B12)); \
    FMA2(acc[0],  PL0, d00); FMA2(acc[1],  PL0, d01); FMA2(acc[2],  PL0, d02); \
    FMA2(acc[3],  PL1, d00); FMA2(acc[4],  PL1, d01); FMA2(acc[5],  PL1, d02); \
    FMA2(acc[6],  PL2, d00); FMA2(acc[7],  PL2, d01); FMA2(acc[8],  PL2, d02); \
    FMA2(acc[9],  PL0, d10); FMA2(acc[10], PL0, d11); FMA2(acc[11], PL0, d12); \
    FMA2(acc[12], PL1, d10); FMA2(acc[13], PL1, d11); FMA2(acc[14], PL1, d12); \
    FMA2(acc[15], PL2, d10); FMA2(acc[16], PL2, d11); FMA2(acc[17], PL2, d12); \
} while (0)

#define PAW(t) ((t) < 4 ? PA[(t)]  : PAn[(t) - 4])
#define B0W(t) ((t) < 4 ? b0c[(t)] : b0n[(t) - 4])
#define B1W(t) ((t) < 4 ? b1c[(t)] : b1n[(t) - 4])

// Gram matrix of the 18 shifted views via 6 stream-pair-blocks; also folds in
// the per-view first-moment sums (row-total minus edges trick).
__global__ void __launch_bounds__(96, 6) k_cov() {
    int p     = blockIdx.x;
    int strip = blockIdx.y;
    int ys = strip * SH;
    int sh = min(SH, NH - ys);

    __shared__ __align__(16) float sbuf[2 * 18 * SPITCH];  // la rows | pr rows
    __shared__ float srs[36];
    float* sla = sbuf;
    float* spr = sbuf + 18 * SPITCH;

    int tid = threadIdx.x;
    int row = tid & 15;
    int pb  = tid >> 4;
    const float* la = g_la + p * P * P;
    const float* pr = g_pr + p * P * P;

    int nrows = sh + 2;
    for (int i = tid; i < nrows * P; i += 96) {
        int r = i / P, x = i - r * P;
        sla[r * SPITCH + x] = la[(ys + r) * P + x];
        spr[r * SPITCH + x] = pr[(ys + r) * P + x];
    }
    __syncthreads();

    ull acc[18];
#pragma unroll
    for (int k = 0; k < 18; k++) acc[k] = 0ULL;

    if (row < sh) {
        int gi = c_PBI[pb], gj = c_PBJ[pb];
        int sA0 = 2 * gi, sA1 = 2 * gi + 1, sB0 = 2 * gj, sB1 = 2 * gj + 1;
        const float* pA0 = ((sA0 < 3) ? sla : spr) + ((sA0 < 3 ? sA0 : sA0 - 3) + row) * SPITCH;
        const float* pA1 = ((sA1 < 3) ? sla : spr) + ((sA1 < 3 ? sA1 : sA1 - 3) + row) * SPITCH;
        const float* pB0 = ((sB0 < 3) ? sla : spr) + ((sB0 < 3 ? sB0 : sB0 - 3) + row) * SPITCH;
        const float* pB1 = ((sB1 < 3) ? sla : spr) + ((sB1 < 3 ? sB1 : sB1 - 3) + row) * SPITCH;

        float4 va = *(const float4*)(pA0);
        float4 vb = *(const float4*)(pA1);
        ull PA[4] = { pk2(va.x, vb.x), pk2(va.y, vb.y), pk2(va.z, vb.z), pk2(va.w, vb.w) };
        float4 v0 = *(const float4*)(pB0);
        float4 v1 = *(const float4*)(pB1);
        float b0c[4] = { v0.x, v0.y, v0.z, v0.w };
        float b1c[4] = { v1.x, v1.y, v1.z, v1.w };

        for (int x = 0; x + 4 <= NH - 1; x += 4) {   // steps 0..167
            va = *(const float4*)(pA0 + x + 4);
            vb = *(const float4*)(pA1 + x + 4);
            ull PAn[4] = { pk2(va.x, vb.x), pk2(va.y, vb.y), pk2(va.z, vb.z), pk2(va.w, vb.w) };
            v0 = *(const float4*)(pB0 + x + 4);
            v1 = *(const float4*)(pB1 + x + 4);
            float b0n[4] = { v0.x, v0.y, v0.z, v0.w };
            float b1n[4] = { v1.x, v1.y, v1.z, v1.w };
#pragma unroll
            for (int s = 0; s < 4; s++)
                DOSTEP(PAW(s), PAW(s + 1), PAW(s + 2),
                       B0W(s), B0W(s + 1), B0W(s + 2),
                       B1W(s), B1W(s + 1), B1W(s + 2));
#pragma unroll
            for (int t = 0; t < 4; t++) { PA[t] = PAn[t]; b0c[t] = b0n[t]; b1c[t] = b1n[t]; }
        }
        // tail step x = 168 (positions 168..170)
        DOSTEP(PA[0], PA[1], PA[2], b0c[0], b0c[1], b0c[2], b1c[0], b1c[1], b1c[2]);
    }

    // ---- folded first-moment sums (row totals minus edge elements) ----
    if (tid < 36) {
        int mp = tid / 18, r = tid % 18;
        float T = 0.f;
        if (r < sh + 2) {
            const float* rowp = (mp ? spr : sla) + r * SPITCH;
            for (int x = 0; x < P; x++) T += rowp[x];
        }
        srs[tid] = T;
    }
    __syncthreads();
    if (tid < 18) {
        int mp = tid / 9, dd = tid % 9, dy = dd / 3, dx = dd % 3;
        const float* base = mp ? spr : sla;
        float part = 0.f;
        for (int yl = 0; yl < sh; yl++) {
            int r = yl + dy;
            const float* rowp = base + r * SPITCH;
            float T = srs[mp * 18 + r];
            float rs = (dx == 0) ? T - rowp[169] - rowp[170]
                     : (dx == 1) ? T - rowp[0]   - rowp[170]
                     :             T - rowp[0]   - rowp[1];
            part += rs;
        }
        atomicAdd(&g_sums[p * 18 + tid], (double)part);
    }
    __syncthreads();

    // ---- reduce 96x36 partials over the 16 rows, flush to g_S ----
    float* red = sbuf;             // overlay (96*36 floats)
#pragma unroll
    for (int k = 0; k < 18; k++) {
        float lo, hi;
        asm("mov.b64 {%0, %1}, %2;" : "=f"(lo), "=f"(hi) : "l"(acc[k]));
        red[tid * 36 + k]      = lo;   // i = 0 (stream 2gi)
        red[tid * 36 + 18 + k] = hi;   // i = 1 (stream 2gi+1)
    }
    __syncthreads();
    for (int o = tid; o < 216; o += 96) {
        int pb2 = o / 36, q = o % 36;
        float ssum = 0.f;
#pragma unroll
        for (int r2 = 0; r2 < 16; r2++) ssum += red[(pb2 * 16 + r2) * 36 + q];
        int i = q / 18, k = q % 18;
        int j = k / 9, l = (k % 9) / 3, m = k % 3;
        int a = (2 * c_PBI[pb2] + i) * 3 + l;
        int b = (2 * c_PBJ[pb2] + j) * 3 + m;
        atomicAdd(&g_S[p * 324 + a * 18 + b], (double)ssum);
    }
}

// ---------------------------------------------------------------------------
// Warp-parallel 9x9 Cholesky (fp32; matrices are well-conditioned)
__device__ __forceinline__ void chol9f(float* A, int lane) {
    for (int k = 0; k < 9; k++) {
        if (lane == 0) A[k * 9 + k] = sqrtf(A[k * 9 + k]);
        __syncwarp();
        float rd = __fdividef(1.f, A[k * 9 + k]);
        if (lane > k && lane < 9) A[lane * 9 + k] *= rd;
        __syncwarp();
        for (int idx = lane; idx < 81; idx += 32) {
            int i = idx / 9, j = idx % 9;
            if (j > k && j <= i) A[i * 9 + j] -= A[i * 9 + k] * A[j * 9 + k];
        }
        __syncwarp();
    }
}

// One warp per (n,c): assemble covariances in double, solve in float (proven
// path). Last-finishing block also does the final reduction.
__global__ void __launch_bounds__(32) k_solve(float* __restrict__ out) {
    int p    = blockIdx.x;
    int lane = threadIdx.x;
    __shared__ float A[81], B[81], C2[81], V[81];
    __shared__ unsigned int ticket;
    const double* S  = g_S    + p * 324;
    const double* sm = g_sums + p * 18;
    const double invM = 1.0 / (double)MM;
    for (int idx = lane; idx < 81; idx += 32) {
        int i = idx / 9, j = idx % 9;
        int a = 9 + i, b = 9 + j;
        int hi = a > b ? a : b, lo = a > b ? b : a;
        A[idx] = (float)(S[hi * 18 + lo] - sm[a] * sm[b] * invM + (i == j ? D_ALPHA : 0.0));
        B[idx] = (float)(S[(9 + j) * 18 + i] - sm[i] * sm[9 + j] * invM);   // cross[d][e]
        hi = i > j ? i : j; lo = i > j ? j : i;
        C2[idx] = (float)(S[hi * 18 + lo] - sm[i] * sm[j] * invM);          // la_cov
    }
    __syncwarp();
    chol9f(A, lane);
    if (lane < 9) {   // forward solve L V = cross^T (column d per lane)
        int d = lane;
        for (int e = 0; e < 9; e++) {
            float t = B[d * 9 + e];
            for (int j = 0; j < e; j++) t -= A[e * 9 + j] * V[j * 9 + d];
            V[e * 9 + d] = t * __fdividef(1.f, A[e * 9 + e]);
        }
    }
    __syncwarp();
    for (int idx = lane; idx < 81; idx += 32) {   // appro_var = la_cov - V^T V + aI
        int i = idx / 9, j = idx % 9;
        float t = C2[idx];
#pragma unroll
        for (int k = 0; k < 9; k++) t -= V[k * 9 + i] * V[k * 9 + j];
        if (i == j) t += (float)D_ALPHA;
        B[idx] = t;
    }
    __syncwarp();
    chol9f(B, lane);
    float lsum = (lane < 9) ? logf(B[lane * 9 + lane]) : 0.f;   // 0.5*logdet
    for (int off = 16; off > 0; off >>= 1)
        lsum += __shfl_down_sync(0xffffffffu, lsum, off);
    if (lane == 0) g_rmi[p] = (double)lsum;

    // ---- last-block final reduction (threadFenceReduction pattern) ----
    __threadfence();
    if (lane == 0) ticket = atomicAdd(&g_ctr, 1u);
    __syncwarp();
    if (ticket == NPROB - 1) {
        double rs = 0.0, bs = 0.0, vs = 0.0;
        for (int i = lane; i < NPROB; i += 32) rs += __ldcg(&g_rmi[i]);
        for (int i = lane; i < NBLK; i += 32) {
            float2 pv = __ldcg(&g_part[i]);
            bs += (double)pv.x; vs += (double)pv.y;
        }
#pragma unroll
        for (int off = 16; off > 0; off >>= 1) {
            rs += __shfl_down_sync(0xffffffffu, rs, off);
            bs += __shfl_down_sync(0xffffffffu, bs, off);
            vs += __shfl_down_sync(0xffffffffu, vs, off);
        }
        if (lane == 0) {
            double rmi = rs / 36.0;                 // mean over batch(4)/half_d(9)
            double bce = bs / (vs + 1.0);
            out[0] = (float)(0.5 * bce + 0.5 * rmi);
            g_ctr = 0;                              // reset for next graph replay
        }
    }
}

// ---------------------------------------------------------------------------
extern "C" void kernel_launch(void* const* d_in, const int* in_sizes, int n_in,
                              void* d_out, int out_size) {
    const float* logits = (const float*)d_in[0];
    const int*   labels = (const int*)d_in[1];
    float* out = (float*)d_out;

    k_pool_bce<<<dim3(P, BN), 192>>>(logits, labels);
    k_cov<<<dim3(NPROB, NSTRIP), 96>>>();
    k_solve<<<NPROB, 32>>>(out);
}

// round 14
// speedup vs baseline: 1.0364x; 1.0335x over previous
#include <cuda_runtime.h>
#include <math.h>

typedef unsigned long long ull;

// Problem constants
static constexpr int BN = 4;            // batch
static constexpr int NC = 21;           // classes
static constexpr int H  = 512;
static constexpr int W  = 512;
static constexpr int P  = 171;          // pooled H/W
static constexpr int NH = 169;          // cropped size P - (radius-1)
static constexpr int NPROB = BN * NC;   // 84
static constexpr int MM = NH * NH;      // 28561
static constexpr double D_ALPHA = 5e-4;
static constexpr float  CLIP_MIN = 1e-6f;
static constexpr float  NEG_BIG  = -1e30f;
static constexpr int SPITCH = 172;      // smem pitch (floats, mult of 4)
static constexpr int SH = 16;           // strip height for k_cov
static constexpr int NSTRIP = (NH + SH - 1) / SH;  // 11
static constexpr int NBLK = P * BN;     // 684 pool blocks

// Scratch (static device globals: no allocation allowed)
__device__ float  g_la[NPROB * P * P];      // pooled one-hot labels
__device__ float  g_pr[NPROB * P * P];      // pooled probs
__device__ double g_S[NPROB * 18 * 18];     // raw second-moment Gram
__device__ double g_sums[NPROB * 18];       // raw first moments
__device__ float2 g_part[NBLK];             // per-block (bce, valid) - plain stores
__device__ double g_rmi[NPROB];
__device__ unsigned int g_ctr;              // last-block ticket (self-resetting)

// stream-pair-block map: 6 lower-tri pairs of the 3 stream-groups
__constant__ int c_PBI[6] = {0, 1, 1, 2, 2, 2};
__constant__ int c_PBJ[6] = {0, 0, 1, 0, 1, 2};

// ---------------------------------------------------------------------------
// Fused: BCE partials + sigmoid + one-hot + 3x3/s3/p1 maxpool. Also zeroes
// the g_S/g_sums slices consumed by later kernels.
// Pipelined double buffering (R12) + pre-biased logits: masked/pad logits
// carry -1e30 (softplus term -> 0, loses every max) so the inner loop has NO
// mask logic; one-hot pooled map via per-window label bitmask (R8-validated);
// 9 softplus logs batched as one log of the product (R12-validated).
__global__ void __launch_bounds__(192) k_pool_bce(const float* __restrict__ logits,
                                                  const int*   __restrict__ labels) {
    int py = blockIdx.x;        // 0..170
    int n  = blockIdx.y;        // 0..3
    int tid = threadIdx.x;
    int bid = n * P + py;

    // zero scratch consumed by k_cov (684 blocks x 42 = 28728 doubles exact)
    if (tid < 42) {
        int zi = bid * 42 + tid;
        if (zi < NPROB * 324) g_S[zi] = 0.0;
        else                  g_sums[zi - NPROB * 324] = 0.0;
    }

    __shared__ __align__(16) float slog[2][3][520];   // double-buffered, data at 4..515
    __shared__ __align__(16) float sbias[3][520];     // 0 (valid) or -1e30 (masked)
    __shared__ int   slab[3][520];
    __shared__ float warp_b[6], warp_v[6];

    int y0 = py * 3 - 1;
    const int* lb = labels + (long)n * H * W;

    // stage labels -> lab id + bias (pads get l=NC -> bias -1e30)
    for (int i = tid; i < 3 * 520; i += 192) {
        int r = i / 520, x = i - r * 520;
        int xx = x - 4;
        int y  = y0 + r;
        bool v = ((unsigned)y < (unsigned)H) && ((unsigned)xx < (unsigned)W);
        int  l = v ? lb[y * W + xx] : NC;
        slab[r][x]  = l;
        sbias[r][x] = (l < NC) ? 0.f : NEG_BIG;
    }
    // preset pad columns of BOTH logit buffers to -1e30 (never re-written)
    if (tid < 48) {
        int b = tid / 24, rem = tid - b * 24;
        int r = rem / 8, j = rem - r * 8;
        int x = (j < 4) ? j : 512 + j;
        slog[b][r][x] = NEG_BIG;
    }

    // fixed per-thread staging slots: i0 = tid, i1 = tid + 192
    int r0 = tid >> 7,         j0 = tid & 127;          // r0 in {0,1}
    int r1 = (tid + 192) >> 7, j1 = (tid + 192) & 127;  // r1 in {1,2}
    bool v0ok = (unsigned)(y0 + r0) < (unsigned)H;
    bool v1ok = (unsigned)(y0 + r1) < (unsigned)H;
    const long HW = (long)H * W;
    const float4* p0 = (const float4*)(logits + (long)(n * NC) * HW + (long)(y0 + r0) * W) + j0;
    const float4* p1 = (const float4*)(logits + (long)(n * NC) * HW + (long)(y0 + r1) * W) + j1;
    const long HW4 = HW / 4;

    // preload class 0 (bias not applied yet; sbias not ready before sync)
    float4 a0 = make_float4(NEG_BIG, NEG_BIG, NEG_BIG, NEG_BIG), b0 = a0;
    if (v0ok) a0 = *p0;
    if (v1ok) b0 = *p1;
    p0 += HW4; p1 += HW4;
    __syncthreads();

    // loop-invariant staging biases (registers)
    float4 bs0 = *(const float4*)&sbias[r0][4 + 4 * j0];
    float4 bs1 = *(const float4*)&sbias[r1][4 + 4 * j1];
    a0.x += bs0.x; a0.y += bs0.y; a0.z += bs0.z; a0.w += bs0.w;
    b0.x += bs1.x; b0.y += bs1.y; b0.z += bs1.z; b0.w += bs1.w;
    *(float4*)&slog[0][r0][4 + 4 * j0] = a0;
    *(float4*)&slog[0][r1][4 + 4 * j1] = b0;

    int  px  = tid;
    bool act = px < P;
    int  xb  = 3 * px + 3;
    int lab[9];
    unsigned wmask = 0u;
    float valid_part = 0.f, bce_part = 0.f;
    if (act) {
#pragma unroll
        for (int k = 0; k < 9; k++) {
            int r = k / 3, dx = k % 3;
            int l = slab[r][xb + dx];
            lab[k] = l;
            if (l < NC) { wmask |= 1u << l; valid_part += 1.f; }
        }
    }
    __syncthreads();

    const long PPP = (long)P * P;
    float* pla = g_la + (long)(n * NC) * PPP + (long)py * P + px;
    float* ppr = g_pr + (long)(n * NC) * PPP + (long)py * P + px;

    for (int c = 0; c < NC; c++) {
        // issue next class's loads early (latency hidden under compute)
        float4 na = make_float4(NEG_BIG, NEG_BIG, NEG_BIG, NEG_BIG), nb = na;
        if (c + 1 < NC) {
            if (v0ok) na = *p0;
            if (v1ok) nb = *p1;
            p0 += HW4; p1 += HW4;
        }
        if (act) {
            const float* sl = &slog[c & 1][0][xb];
            float mv = NEG_BIG, lin = 0.f, xs = 0.f, prod = 1.f;
#pragma unroll
            for (int k = 0; k < 9; k++) {
                int r = k / 3, dx = k % 3;
                float xv = sl[r * 520 + dx];
                mv   = fmaxf(mv, xv);
                lin += fmaxf(xv, 0.f);                 // masked: 0
                if (lab[k] == c) xs += xv;             // lab==c implies valid
                float e = __expf(-fabsf(xv));          // masked: 0
                prod *= (1.f + e);                     // masked: x1
            }
            bce_part += lin - xs + __logf(prod);       // ONE log per window
            float em  = __expf(-fabsf(mv));
            float rc  = __fdividef(1.f, 1.f + em);
            float sig = (mv >= 0.f) ? rc : em * rc;    // mv=-1e30 -> 0
            *pla = (float)((wmask >> c) & 1u);
            *ppr = sig + CLIP_MIN;
        }
        pla += PPP; ppr += PPP;
        if (c + 1 < NC) {   // biased STS after compute (waits on LDG here)
            na.x += bs0.x; na.y += bs0.y; na.z += bs0.z; na.w += bs0.w;
            nb.x += bs1.x; nb.y += bs1.y; nb.z += bs1.z; nb.w += bs1.w;
            *(float4*)&slog[(c + 1) & 1][r0][4 + 4 * j0] = na;
            *(float4*)&slog[(c + 1) & 1][r1][4 + 4 * j1] = nb;
        }
        __syncthreads();
    }

#pragma unroll
    for (int off = 16; off > 0; off >>= 1) {
        bce_part   += __shfl_down_sync(0xffffffffu, bce_part,   off);
        valid_part += __shfl_down_sync(0xffffffffu, valid_part, off);
    }
    int wid = tid >> 5, lane = tid & 31;
    if (lane == 0) { warp_b[wid] = bce_part; warp_v[wid] = valid_part; }
    __syncthreads();
    if (tid == 0) {
        float b = 0.f, v = 0.f;
#pragma unroll
        for (int w = 0; w < 6; w++) { b += warp_b[w]; v += warp_v[w]; }
        g_part[bid] = make_float2(b, v);   // plain store, no init needed
    }
}

// ---------------------------------------------------------------------------
// f32x2 helpers
__device__ __forceinline__ ull pk2(float lo, float hi) {
    ull r; asm("mov.b64 %0, {%1, %2};" : "=l"(r) : "f"(lo), "f"(hi)); return r;
}
#define FMA2(d, a, b) asm("fma.rn.f32x2 %0, %1, %2, %0;" : "+l"(d) : "l"(a), "l"(b))

// One step: acc[j*9+l*3+m] += PA[l-pos] * dup(Bj[m-pos])
#define DOSTEP(PL0, PL1, PL2, B00, B01, B02, B10, B11, B12) do {              \
    ull d00 = pk2((B00),(B00)), d01 = pk2((B01),(B01)), d02 = pk2((B02),(B02)); \
    ull d10 = pk2((B10),(B10)), d11 = pk2((B11),(B11)), d12 = pk2((B12),(B12)); \
    FMA2(acc[0],  PL0, d00); FMA2(acc[1],  PL0, d01); FMA2(acc[2],  PL0, d02); \
    FMA2(acc[3],  PL1, d00); FMA2(acc[4],  PL1, d01); FMA2(acc[5],  PL1, d02); \
    FMA2(acc[6],  PL2, d00); FMA2(acc[7],  PL2, d01); FMA2(acc[8],  PL2, d02); \
    FMA2(acc[9],  PL0, d10); FMA2(acc[10], PL0, d11); FMA2(acc[11], PL0, d12); \
    FMA2(acc[12], PL1, d10); FMA2(acc[13], PL1, d11); FMA2(acc[14], PL1, d12); \
    FMA2(acc[15], PL2, d10); FMA2(acc[16], PL2, d11); FMA2(acc[17], PL2, d12); \
} while (0)

#define PAW(t) ((t) < 4 ? PA[(t)]  : PAn[(t) - 4])
#define B0W(t) ((t) < 4 ? b0c[(t)] : b0n[(t) - 4])
#define B1W(t) ((t) < 4 ? b1c[(t)] : b1n[(t) - 4])

// Gram matrix of the 18 shifted views via 6 stream-pair-blocks; also folds in
// the per-view first-moment sums (row-total minus edges trick).
__global__ void __launch_bounds__(96, 6) k_cov() {
    int p     = blockIdx.x;
    int strip = blockIdx.y;
    int ys = strip * SH;
    int sh = min(SH, NH - ys);

    __shared__ __align__(16) float sbuf[2 * 18 * SPITCH];  // la rows | pr rows
    __shared__ float srs[36];
    float* sla = sbuf;
    float* spr = sbuf + 18 * SPITCH;

    int tid = threadIdx.x;
    int row = tid & 15;
    int pb  = tid >> 4;
    const float* la = g_la + p * P * P;
    const float* pr = g_pr + p * P * P;

    int nrows = sh + 2;
    for (int i = tid; i < nrows * P; i += 96) {
        int r = i / P, x = i - r * P;
        sla[r * SPITCH + x] = la[(ys + r) * P + x];
        spr[r * SPITCH + x] = pr[(ys + r) * P + x];
    }
    __syncthreads();

    ull acc[18];
#pragma unroll
    for (int k = 0; k < 18; k++) acc[k] = 0ULL;

    if (row < sh) {
        int gi = c_PBI[pb], gj = c_PBJ[pb];
        int sA0 = 2 * gi, sA1 = 2 * gi + 1, sB0 = 2 * gj, sB1 = 2 * gj + 1;
        const float* pA0 = ((sA0 < 3) ? sla : spr) + ((sA0 < 3 ? sA0 : sA0 - 3) + row) * SPITCH;
        const float* pA1 = ((sA1 < 3) ? sla : spr) + ((sA1 < 3 ? sA1 : sA1 - 3) + row) * SPITCH;
        const float* pB0 = ((sB0 < 3) ? sla : spr) + ((sB0 < 3 ? sB0 : sB0 - 3) + row) * SPITCH;
        const float* pB1 = ((sB1 < 3) ? sla : spr) + ((sB1 < 3 ? sB1 : sB1 - 3) + row) * SPITCH;

        float4 va = *(const float4*)(pA0);
        float4 vb = *(const float4*)(pA1);
        ull PA[4] = { pk2(va.x, vb.x), pk2(va.y, vb.y), pk2(va.z, vb.z), pk2(va.w, vb.w) };
        float4 v0 = *(const float4*)(pB0);
        float4 v1 = *(const float4*)(pB1);
        float b0c[4] = { v0.x, v0.y, v0.z, v0.w };
        float b1c[4] = { v1.x, v1.y, v1.z, v1.w };

        for (int x = 0; x + 4 <= NH - 1; x += 4) {   // steps 0..167
            va = *(const float4*)(pA0 + x + 4);
            vb = *(const float4*)(pA1 + x + 4);
            ull PAn[4] = { pk2(va.x, vb.x), pk2(va.y, vb.y), pk2(va.z, vb.z), pk2(va.w, vb.w) };
            v0 = *(const float4*)(pB0 + x + 4);
            v1 = *(const float4*)(pB1 + x + 4);
            float b0n[4] = { v0.x, v0.y, v0.z, v0.w };
            float b1n[4] = { v1.x, v1.y, v1.z, v1.w };
#pragma unroll
            for (int s = 0; s < 4; s++)
                DOSTEP(PAW(s), PAW(s + 1), PAW(s + 2),
                       B0W(s), B0W(s + 1), B0W(s + 2),
                       B1W(s), B1W(s + 1), B1W(s + 2));
#pragma unroll
            for (int t = 0; t < 4; t++) { PA[t] = PAn[t]; b0c[t] = b0n[t]; b1c[t] = b1n[t]; }
        }
        // tail step x = 168 (positions 168..170)
        DOSTEP(PA[0], PA[1], PA[2], b0c[0], b0c[1], b0c[2], b1c[0], b1c[1], b1c[2]);
    }

    // ---- folded first-moment sums (row totals minus edge elements) ----
    if (tid < 36) {
        int mp = tid / 18, r = tid % 18;
        float T = 0.f;
        if (r < sh + 2) {
            const float* rowp = (mp ? spr : sla) + r * SPITCH;
            for (int x = 0; x < P; x++) T += rowp[x];
        }
        srs[tid] = T;
    }
    __syncthreads();
    if (tid < 18) {
        int mp = tid / 9, dd = tid % 9, dy = dd / 3, dx = dd % 3;
        const float* base = mp ? spr : sla;
        float part = 0.f;
        for (int yl = 0; yl < sh; yl++) {
            int r = yl + dy;
            const float* rowp = base + r * SPITCH;
            float T = srs[mp * 18 + r];
            float rs = (dx == 0) ? T - rowp[169] - rowp[170]
                     : (dx == 1) ? T - rowp[0]   - rowp[170]
                     :             T - rowp[0]   - rowp[1];
            part += rs;
        }
        atomicAdd(&g_sums[p * 18 + tid], (double)part);
    }
    __syncthreads();

    // ---- reduce 96x36 partials over the 16 rows, flush to g_S ----
    float* red = sbuf;             // overlay (96*36 floats)
#pragma unroll
    for (int k = 0; k < 18; k++) {
        float lo, hi;
        asm("mov.b64 {%0, %1}, %2;" : "=f"(lo), "=f"(hi) : "l"(acc[k]));
        red[tid * 36 + k]      = lo;   // i = 0 (stream 2gi)
        red[tid * 36 + 18 + k] = hi;   // i = 1 (stream 2gi+1)
    }
    __syncthreads();
    for (int o = tid; o < 216; o += 96) {
        int pb2 = o / 36, q = o % 36;
        float ssum = 0.f;
#pragma unroll
        for (int r2 = 0; r2 < 16; r2++) ssum += red[(pb2 * 16 + r2) * 36 + q];
        int i = q / 18, k = q % 18;
        int j = k / 9, l = (k % 9) / 3, m = k % 3;
        int a = (2 * c_PBI[pb2] + i) * 3 + l;
        int b = (2 * c_PBJ[pb2] + j) * 3 + m;
        atomicAdd(&g_S[p * 324 + a * 18 + b], (double)ssum);
    }
}

// ---------------------------------------------------------------------------
// Warp-parallel 9x9 Cholesky (fp32; matrices are well-conditioned)
__device__ __forceinline__ void chol9f(float* A, int lane) {
    for (int k = 0; k < 9; k++) {
        if (lane == 0) A[k * 9 + k] = sqrtf(A[k * 9 + k]);
        __syncwarp();
        float rd = __fdividef(1.f, A[k * 9 + k]);
        if (lane > k && lane < 9) A[lane * 9 + k] *= rd;
        __syncwarp();
        for (int idx = lane; idx < 81; idx += 32) {
            int i = idx / 9, j = idx % 9;
            if (j > k && j <= i) A[i * 9 + j] -= A[i * 9 + k] * A[j * 9 + k];
        }
        __syncwarp();
    }
}

// One warp per (n,c): assemble covariances in double, solve in float (proven
// path). Last-finishing block also does the final reduction.
__global__ void __launch_bounds__(32) k_solve(float* __restrict__ out) {
    int p    = blockIdx.x;
    int lane = threadIdx.x;
    __shared__ float A[81], B[81], C2[81], V[81];
    __shared__ unsigned int ticket;
    const double* S  = g_S    + p * 324;
    const double* sm = g_sums + p * 18;
    const double invM = 1.0 / (double)MM;
    for (int idx = lane; idx < 81; idx += 32) {
        int i = idx / 9, j = idx % 9;
        int a = 9 + i, b = 9 + j;
        int hi = a > b ? a : b, lo = a > b ? b : a;
        A[idx] = (float)(S[hi * 18 + lo] - sm[a] * sm[b] * invM + (i == j ? D_ALPHA : 0.0));
        B[idx] = (float)(S[(9 + j) * 18 + i] - sm[i] * sm[9 + j] * invM);   // cross[d][e]
        hi = i > j ? i : j; lo = i > j ? j : i;
        C2[idx] = (float)(S[hi * 18 + lo] - sm[i] * sm[j] * invM);          // la_cov
    }
    __syncwarp();
    chol9f(A, lane);
    if (lane < 9) {   // forward solve L V = cross^T (column d per lane)
        int d = lane;
        for (int e = 0; e < 9; e++) {
            float t = B[d * 9 + e];
            for (int j = 0; j < e; j++) t -= A[e * 9 + j] * V[j * 9 + d];
            V[e * 9 + d] = t * __fdividef(1.f, A[e * 9 + e]);
        }
    }
    __syncwarp();
    for (int idx = lane; idx < 81; idx += 32) {   // appro_var = la_cov - V^T V + aI
        int i = idx / 9, j = idx % 9;
        float t = C2[idx];
#pragma unroll
        for (int k = 0; k < 9; k++) t -= V[k * 9 + i] * V[k * 9 + j];
        if (i == j) t += (float)D_ALPHA;
        B[idx] = t;
    }
    __syncwarp();
    chol9f(B, lane);
    float lsum = (lane < 9) ? logf(B[lane * 9 + lane]) : 0.f;   // 0.5*logdet
    for (int off = 16; off > 0; off >>= 1)
        lsum += __shfl_down_sync(0xffffffffu, lsum, off);
    if (lane == 0) g_rmi[p] = (double)lsum;

    // ---- last-block final reduction (threadFenceReduction pattern) ----
    __threadfence();
    if (lane == 0) ticket = atomicAdd(&g_ctr, 1u);
    __syncwarp();
    if (ticket == NPROB - 1) {
        double rs = 0.0, bs = 0.0, vs = 0.0;
        for (int i = lane; i < NPROB; i += 32) rs += __ldcg(&g_rmi[i]);
        for (int i = lane; i < NBLK; i += 32) {
            float2 pv = __ldcg(&g_part[i]);
            bs += (double)pv.x; vs += (double)pv.y;
        }
#pragma unroll
        for (int off = 16; off > 0; off >>= 1) {
            rs += __shfl_down_sync(0xffffffffu, rs, off);
            bs += __shfl_down_sync(0xffffffffu, bs, off);
            vs += __shfl_down_sync(0xffffffffu, vs, off);
        }
        if (lane == 0) {
            double rmi = rs / 36.0;                 // mean over batch(4)/half_d(9)
            double bce = bs / (vs + 1.0);
            out[0] = (float)(0.5 * bce + 0.5 * rmi);
            g_ctr = 0;                              // reset for next graph replay
        }
    }
}

// ---------------------------------------------------------------------------
extern "C" void kernel_launch(void* const* d_in, const int* in_sizes, int n_in,
                              void* d_out, int out_size) {
    const float* logits = (const float*)d_in[0];
    const int*   labels = (const int*)d_in[1];
    float* out = (float*)d_out;

    k_pool_bce<<<dim3(P, BN), 192>>>(logits, labels);
    k_cov<<<dim3(NPROB, NSTRIP), 96>>>();
    k_solve<<<NPROB, 32>>>(out);
}

// round 15
// speedup vs baseline: 1.0756x; 1.0378x over previous
#include <cuda_runtime.h>
#include <math.h>

typedef unsigned long long ull;

// Problem constants
static constexpr int BN = 4;            // batch
static constexpr int NC = 21;           // classes
static constexpr int H  = 512;
static constexpr int W  = 512;
static constexpr int P  = 171;          // pooled H/W
static constexpr int NH = 169;          // cropped size P - (radius-1)
static constexpr int NPROB = BN * NC;   // 84
static constexpr int MM = NH * NH;      // 28561
static constexpr double D_ALPHA = 5e-4;
static constexpr float  CLIP_MIN = 1e-6f;
static constexpr float  NEG_BIG  = -1e30f;
static constexpr int SPITCH = 172;      // smem pitch (floats, mult of 4)
static constexpr int SH = 16;           // strip height for k_cov
static constexpr int NSTRIP = (NH + SH - 1) / SH;  // 11
static constexpr int NBLK = P * BN;     // 684 pool blocks

// Scratch (static device globals: no allocation allowed)
__device__ float  g_la[NPROB * P * P];      // pooled one-hot labels
__device__ float  g_pr[NPROB * P * P];      // pooled probs
__device__ double g_S[NPROB * 18 * 18];     // raw second-moment Gram
__device__ double g_sums[NPROB * 18];       // raw first moments
__device__ float2 g_part[NBLK];             // per-block (bce, valid) - plain stores
__device__ double g_rmi[NPROB];
__device__ unsigned int g_ctr;              // last-block ticket (self-resetting)

// stream-pair-block map: 6 lower-tri pairs of the 3 stream-groups
__constant__ int c_PBI[6] = {0, 1, 1, 2, 2, 2};
__constant__ int c_PBJ[6] = {0, 0, 1, 0, 1, 2};

// ---------------------------------------------------------------------------
// Fused: BCE partials + sigmoid + one-hot + 3x3/s3/p1 maxpool (R14-exact).
__global__ void __launch_bounds__(192) k_pool_bce(const float* __restrict__ logits,
                                                  const int*   __restrict__ labels) {
    int py = blockIdx.x;        // 0..170
    int n  = blockIdx.y;        // 0..3
    int tid = threadIdx.x;
    int bid = n * P + py;

    // zero scratch consumed by k_cov (684 blocks x 42 = 28728 doubles exact)
    if (tid < 42) {
        int zi = bid * 42 + tid;
        if (zi < NPROB * 324) g_S[zi] = 0.0;
        else                  g_sums[zi - NPROB * 324] = 0.0;
    }

    __shared__ __align__(16) float slog[2][3][520];   // double-buffered, data at 4..515
    __shared__ __align__(16) float sbias[3][520];     // 0 (valid) or -1e30 (masked)
    __shared__ int   slab[3][520];
    __shared__ float warp_b[6], warp_v[6];

    int y0 = py * 3 - 1;
    const int* lb = labels + (long)n * H * W;

    for (int i = tid; i < 3 * 520; i += 192) {
        int r = i / 520, x = i - r * 520;
        int xx = x - 4;
        int y  = y0 + r;
        bool v = ((unsigned)y < (unsigned)H) && ((unsigned)xx < (unsigned)W);
        int  l = v ? lb[y * W + xx] : NC;
        slab[r][x]  = l;
        sbias[r][x] = (l < NC) ? 0.f : NEG_BIG;
    }
    if (tid < 48) {
        int b = tid / 24, rem = tid - b * 24;
        int r = rem / 8, j = rem - r * 8;
        int x = (j < 4) ? j : 512 + j;
        slog[b][r][x] = NEG_BIG;
    }

    int r0 = tid >> 7,         j0 = tid & 127;          // r0 in {0,1}
    int r1 = (tid + 192) >> 7, j1 = (tid + 192) & 127;  // r1 in {1,2}
    bool v0ok = (unsigned)(y0 + r0) < (unsigned)H;
    bool v1ok = (unsigned)(y0 + r1) < (unsigned)H;
    const long HW = (long)H * W;
    const float4* p0 = (const float4*)(logits + (long)(n * NC) * HW + (long)(y0 + r0) * W) + j0;
    const float4* p1 = (const float4*)(logits + (long)(n * NC) * HW + (long)(y0 + r1) * W) + j1;
    const long HW4 = HW / 4;

    float4 a0 = make_float4(NEG_BIG, NEG_BIG, NEG_BIG, NEG_BIG), b0 = a0;
    if (v0ok) a0 = *p0;
    if (v1ok) b0 = *p1;
    p0 += HW4; p1 += HW4;
    __syncthreads();

    float4 bs0 = *(const float4*)&sbias[r0][4 + 4 * j0];
    float4 bs1 = *(const float4*)&sbias[r1][4 + 4 * j1];
    a0.x += bs0.x; a0.y += bs0.y; a0.z += bs0.z; a0.w += bs0.w;
    b0.x += bs1.x; b0.y += bs1.y; b0.z += bs1.z; b0.w += bs1.w;
    *(float4*)&slog[0][r0][4 + 4 * j0] = a0;
    *(float4*)&slog[0][r1][4 + 4 * j1] = b0;

    int  px  = tid;
    bool act = px < P;
    int  xb  = 3 * px + 3;
    int lab[9];
    unsigned wmask = 0u;
    float valid_part = 0.f, bce_part = 0.f;
    if (act) {
#pragma unroll
        for (int k = 0; k < 9; k++) {
            int r = k / 3, dx = k % 3;
            int l = slab[r][xb + dx];
            lab[k] = l;
            if (l < NC) { wmask |= 1u << l; valid_part += 1.f; }
        }
    }
    __syncthreads();

    const long PPP = (long)P * P;
    float* pla = g_la + (long)(n * NC) * PPP + (long)py * P + px;
    float* ppr = g_pr + (long)(n * NC) * PPP + (long)py * P + px;

    for (int c = 0; c < NC; c++) {
        float4 na = make_float4(NEG_BIG, NEG_BIG, NEG_BIG, NEG_BIG), nb = na;
        if (c + 1 < NC) {
            if (v0ok) na = *p0;
            if (v1ok) nb = *p1;
            p0 += HW4; p1 += HW4;
        }
        if (act) {
            const float* sl = &slog[c & 1][0][xb];
            float mv = NEG_BIG, lin = 0.f, xs = 0.f, prod = 1.f;
#pragma unroll
            for (int k = 0; k < 9; k++) {
                int r = k / 3, dx = k % 3;
                float xv = sl[r * 520 + dx];
                mv   = fmaxf(mv, xv);
                lin += fmaxf(xv, 0.f);
                if (lab[k] == c) xs += xv;
                float e = __expf(-fabsf(xv));
                prod *= (1.f + e);
            }
            bce_part += lin - xs + __logf(prod);
            float em  = __expf(-fabsf(mv));
            float rc  = __fdividef(1.f, 1.f + em);
            float sig = (mv >= 0.f) ? rc : em * rc;
            *pla = (float)((wmask >> c) & 1u);
            *ppr = sig + CLIP_MIN;
        }
        pla += PPP; ppr += PPP;
        if (c + 1 < NC) {
            na.x += bs0.x; na.y += bs0.y; na.z += bs0.z; na.w += bs0.w;
            nb.x += bs1.x; nb.y += bs1.y; nb.z += bs1.z; nb.w += bs1.w;
            *(float4*)&slog[(c + 1) & 1][r0][4 + 4 * j0] = na;
            *(float4*)&slog[(c + 1) & 1][r1][4 + 4 * j1] = nb;
        }
        __syncthreads();
    }

#pragma unroll
    for (int off = 16; off > 0; off >>= 1) {
        bce_part   += __shfl_down_sync(0xffffffffu, bce_part,   off);
        valid_part += __shfl_down_sync(0xffffffffu, valid_part, off);
    }
    int wid = tid >> 5, lane = tid & 31;
    if (lane == 0) { warp_b[wid] = bce_part; warp_v[wid] = valid_part; }
    __syncthreads();
    if (tid == 0) {
        float b = 0.f, v = 0.f;
#pragma unroll
        for (int w = 0; w < 6; w++) { b += warp_b[w]; v += warp_v[w]; }
        g_part[bid] = make_float2(b, v);
    }
}

// ---------------------------------------------------------------------------
// f32x2 helpers
__device__ __forceinline__ ull pk2(float lo, float hi) {
    ull r; asm("mov.b64 %0, {%1, %2};" : "=l"(r) : "f"(lo), "f"(hi)); return r;
}
#define FMA2(d, a, b) asm("fma.rn.f32x2 %0, %1, %2, %0;" : "+l"(d) : "l"(a), "l"(b))

// One step: acc[j*9+l*3+m] += PA[l-pos] * dup(Bj[m-pos])
#define DOSTEP(PL0, PL1, PL2, B00, B01, B02, B10, B11, B12) do {              \
    ull d00 = pk2((B00),(B00)), d01 = pk2((B01),(B01)), d02 = pk2((B02),(B02)); \
    ull d10 = pk2((B10),(B10)), d11 = pk2((B11),(B11)), d12 = pk2((B12),(B12)); \
    FMA2(acc[0],  PL0, d00); FMA2(acc[1],  PL0, d01); FMA2(acc[2],  PL0, d02); \
    FMA2(acc[3],  PL1, d00); FMA2(acc[4],  PL1, d01); FMA2(acc[5],  PL1, d02); \
    FMA2(acc[6],  PL2, d00); FMA2(acc[7],  PL2, d01); FMA2(acc[8],  PL2, d02); \
    FMA2(acc[9],  PL0, d10); FMA2(acc[10], PL0, d11); FMA2(acc[11], PL0, d12); \
    FMA2(acc[12], PL1, d10); FMA2(acc[13], PL1, d11); FMA2(acc[14], PL1, d12); \
    FMA2(acc[15], PL2, d10); FMA2(acc[16], PL2, d11); FMA2(acc[17], PL2, d12); \
} while (0)

#define PAW(t) ((t) < 4 ? PA[(t)]  : PAn[(t) - 4])
#define B0W(t) ((t) < 4 ? b0c[(t)] : b0n[(t) - 4])
#define B1W(t) ((t) < 4 ? b1c[(t)] : b1n[(t) - 4])

// Gram matrix of the 18 shifted views via 6 stream-pair-blocks; also folds in
// the per-view first-moment sums (row-total minus edges trick). (R14-exact)
__global__ void __launch_bounds__(96, 6) k_cov() {
    int p     = blockIdx.x;
    int strip = blockIdx.y;
    int ys = strip * SH;
    int sh = min(SH, NH - ys);

    __shared__ __align__(16) float sbuf[2 * 18 * SPITCH];  // la rows | pr rows
    __shared__ float srs[36];
    float* sla = sbuf;
    float* spr = sbuf + 18 * SPITCH;

    int tid = threadIdx.x;
    int row = tid & 15;
    int pb  = tid >> 4;
    const float* la = g_la + p * P * P;
    const float* pr = g_pr + p * P * P;

    int nrows = sh + 2;
    for (int i = tid; i < nrows * P; i += 96) {
        int r = i / P, x = i - r * P;
        sla[r * SPITCH + x] = la[(ys + r) * P + x];
        spr[r * SPITCH + x] = pr[(ys + r) * P + x];
    }
    __syncthreads();

    ull acc[18];
#pragma unroll
    for (int k = 0; k < 18; k++) acc[k] = 0ULL;

    if (row < sh) {
        int gi = c_PBI[pb], gj = c_PBJ[pb];
        int sA0 = 2 * gi, sA1 = 2 * gi + 1, sB0 = 2 * gj, sB1 = 2 * gj + 1;
        const float* pA0 = ((sA0 < 3) ? sla : spr) + ((sA0 < 3 ? sA0 : sA0 - 3) + row) * SPITCH;
        const float* pA1 = ((sA1 < 3) ? sla : spr) + ((sA1 < 3 ? sA1 : sA1 - 3) + row) * SPITCH;
        const float* pB0 = ((sB0 < 3) ? sla : spr) + ((sB0 < 3 ? sB0 : sB0 - 3) + row) * SPITCH;
        const float* pB1 = ((sB1 < 3) ? sla : spr) + ((sB1 < 3 ? sB1 : sB1 - 3) + row) * SPITCH;

        float4 va = *(const float4*)(pA0);
        float4 vb = *(const float4*)(pA1);
        ull PA[4] = { pk2(va.x, vb.x), pk2(va.y, vb.y), pk2(va.z, vb.z), pk2(va.w, vb.w) };
        float4 v0 = *(const float4*)(pB0);
        float4 v1 = *(const float4*)(pB1);
        float b0c[4] = { v0.x, v0.y, v0.z, v0.w };
        float b1c[4] = { v1.x, v1.y, v1.z, v1.w };

        for (int x = 0; x + 4 <= NH - 1; x += 4) {   // steps 0..167
            va = *(const float4*)(pA0 + x + 4);
            vb = *(const float4*)(pA1 + x + 4);
            ull PAn[4] = { pk2(va.x, vb.x), pk2(va.y, vb.y), pk2(va.z, vb.z), pk2(va.w, vb.w) };
            v0 = *(const float4*)(pB0 + x + 4);
            v1 = *(const float4*)(pB1 + x + 4);
            float b0n[4] = { v0.x, v0.y, v0.z, v0.w };
            float b1n[4] = { v1.x, v1.y, v1.z, v1.w };
#pragma unroll
            for (int s = 0; s < 4; s++)
                DOSTEP(PAW(s), PAW(s + 1), PAW(s + 2),
                       B0W(s), B0W(s + 1), B0W(s + 2),
                       B1W(s), B1W(s + 1), B1W(s + 2));
#pragma unroll
            for (int t = 0; t < 4; t++) { PA[t] = PAn[t]; b0c[t] = b0n[t]; b1c[t] = b1n[t]; }
        }
        DOSTEP(PA[0], PA[1], PA[2], b0c[0], b0c[1], b0c[2], b1c[0], b1c[1], b1c[2]);
    }

    // ---- folded first-moment sums (row totals minus edge elements) ----
    if (tid < 36) {
        int mp = tid / 18, r = tid % 18;
        float T = 0.f;
        if (r < sh + 2) {
            const float* rowp = (mp ? spr : sla) + r * SPITCH;
            for (int x = 0; x < P; x++) T += rowp[x];
        }
        srs[tid] = T;
    }
    __syncthreads();
    if (tid < 18) {
        int mp = tid / 9, dd = tid % 9, dy = dd / 3, dx = dd % 3;
        const float* base = mp ? spr : sla;
        float part = 0.f;
        for (int yl = 0; yl < sh; yl++) {
            int r = yl + dy;
            const float* rowp = base + r * SPITCH;
            float T = srs[mp * 18 + r];
            float rs = (dx == 0) ? T - rowp[169] - rowp[170]
                     : (dx == 1) ? T - rowp[0]   - rowp[170]
                     :             T - rowp[0]   - rowp[1];
            part += rs;
        }
        atomicAdd(&g_sums[p * 18 + tid], (double)part);
    }
    __syncthreads();

    // ---- reduce 96x36 partials over the 16 rows, flush to g_S ----
    float* red = sbuf;             // overlay (96*36 floats)
#pragma unroll
    for (int k = 0; k < 18; k++) {
        float lo, hi;
        asm("mov.b64 {%0, %1}, %2;" : "=f"(lo), "=f"(hi) : "l"(acc[k]));
        red[tid * 36 + k]      = lo;   // i = 0 (stream 2gi)
        red[tid * 36 + 18 + k] = hi;   // i = 1 (stream 2gi+1)
    }
    __syncthreads();
    for (int o = tid; o < 216; o += 96) {
        int pb2 = o / 36, q = o % 36;
        float ssum = 0.f;
#pragma unroll
        for (int r2 = 0; r2 < 16; r2++) ssum += red[(pb2 * 16 + r2) * 36 + q];
        int i = q / 18, k = q % 18;
        int j = k / 9, l = (k % 9) / 3, m = k % 3;
        int a = (2 * c_PBI[pb2] + i) * 3 + l;
        int b = (2 * c_PBJ[pb2] + j) * 3 + m;
        atomicAdd(&g_S[p * 324 + a * 18 + b], (double)ssum);
    }
}

// ---------------------------------------------------------------------------
// Register/shuffle 9x9 Cholesky: lane i (i<9) holds row i in a[0..8] (all
// statically indexed; loops fully unrolled -> no local spills). Cross-lane
// values come from __shfl_sync with compile-time lane ids. Returns sum of
// log(diag of L) (identical on every lane; valid because the broadcast source
// lanes are always < 9).
__device__ __forceinline__ float chol9_reg(float (&a)[9], int lane, bool want_log) {
    float ls = 0.f;
#pragma unroll
    for (int k = 0; k < 9; k++) {
        float dk = __shfl_sync(0xffffffffu, a[k], k);
        float d  = sqrtf(dk);
        if (want_log) ls += logf(d);
        float rd = __fdividef(1.f, d);
        if (lane == k) a[k] = d;
        else           a[k] *= rd;          // rows > k scaled; others unused
#pragma unroll
        for (int j = k + 1; j < 9; j++) {
            float ljk = __shfl_sync(0xffffffffu, a[k], j);   // L[j][k]
            a[j] = fmaf(-a[k], ljk, a[j]);                   // A[i][j] -= L[i][k]L[j][k]
        }
    }
    return ls;
}

// One warp per (n,c): assemble covariances in double (same index mapping as
// the proven smem solver), then all-register shuffle solve. Last-finishing
// block does the final reduction.
__global__ void __launch_bounds__(32) k_solve(float* __restrict__ out) {
    int p    = blockIdx.x;
    int lane = threadIdx.x;
    __shared__ unsigned int ticket;
    const double* S  = g_S    + p * 324;
    const double* sm = g_sums + p * 18;
    const double invM = 1.0 / (double)MM;

    float pa[9];    // row lane of pr_cov+aI  -> L after chol
    float rhs[9];   // rhs[e] = la_pr_cov[lane][e]  (= proven B[d*9+e], d=lane)
    float lc[9];    // row lane of la_cov
    if (lane < 9) {
        int i = lane;
        double smi  = sm[i];
        double smpi = sm[9 + i];
#pragma unroll
        for (int j = 0; j < 9; j++) {
            double smj  = sm[j];
            double smpj = sm[9 + j];
            int a = 9 + i, b = 9 + j;
            int hi = a > b ? a : b, lo = a > b ? b : a;
            pa[j] = (float)(S[hi * 18 + lo] - smpi * smpj * invM + (i == j ? D_ALPHA : 0.0));
            rhs[j] = (float)(S[(9 + j) * 18 + i] - smi * smpj * invM);   // la_pr_cov[i][j]
            hi = i > j ? i : j; lo = i > j ? j : i;
            lc[j] = (float)(S[hi * 18 + lo] - smi * smj * invM);         // la_cov[i][j]
        }
    } else {
#pragma unroll
        for (int j = 0; j < 9; j++) { pa[j] = 1.f; rhs[j] = 0.f; lc[j] = 0.f; }
    }

    // Cholesky of pr_cov+aI (rows in lanes)
    chol9_reg(pa, lane, false);

    // Forward solve L V = la_pr_cov^T: lane d holds V column d in v[e]
    float v[9];
#pragma unroll
    for (int e = 0; e < 9; e++) {
        float t = rhs[e];
#pragma unroll
        for (int j = 0; j < e; j++) {
            float lej = __shfl_sync(0xffffffffu, pa[j], e);   // L[e][j]
            t = fmaf(-lej, v[j], t);
        }
        float lee = __shfl_sync(0xffffffffu, pa[e], e);       // L[e][e]
        v[e] = t * __fdividef(1.f, lee);
    }

    // appro_var row lane: av[j] = la_cov[i][j] - sum_k V[k][i]V[k][j] + aI
    float av[9];
#pragma unroll
    for (int j = 0; j < 9; j++) {
        float t = lc[j];
#pragma unroll
        for (int k = 0; k < 9; k++) {
            float vkj = __shfl_sync(0xffffffffu, v[k], j);    // V[k][j]
            t = fmaf(-v[k], vkj, t);
        }
        if (lane == j) t += (float)D_ALPHA;
        av[j] = t;
    }

    // Cholesky of appro_var + aI; 0.5*logdet = sum log diag (same on all lanes)
    float lsum = chol9_reg(av, lane, true);
    if (lane == 0) g_rmi[p] = (double)lsum;

    // ---- last-block final reduction (threadFenceReduction pattern) ----
    __threadfence();
    if (lane == 0) ticket = atomicAdd(&g_ctr, 1u);
    __syncwarp();
    if (ticket == NPROB - 1) {
        double rs = 0.0, bs = 0.0, vs = 0.0;
        for (int i = lane; i < NPROB; i += 32) rs += __ldcg(&g_rmi[i]);
        for (int i = lane; i < NBLK; i += 32) {
            float2 pv = __ldcg(&g_part[i]);
            bs += (double)pv.x; vs += (double)pv.y;
        }
#pragma unroll
        for (int off = 16; off > 0; off >>= 1) {
            rs += __shfl_down_sync(0xffffffffu, rs, off);
            bs += __shfl_down_sync(0xffffffffu, bs, off);
            vs += __shfl_down_sync(0xffffffffu, vs, off);
        }
        if (lane == 0) {
            double rmi = rs / 36.0;                 // mean over batch(4)/half_d(9)
            double bce = bs / (vs + 1.0);
            out[0] = (float)(0.5 * bce + 0.5 * rmi);
            g_ctr = 0;                              // reset for next graph replay
        }
    }
}

// ---------------------------------------------------------------------------
extern "C" void kernel_launch(void* const* d_in, const int* in_sizes, int n_in,
                              void* d_out, int out_size) {
    const float* logits = (const float*)d_in[0];
    const int*   labels = (const int*)d_in[1];
    float* out = (float*)d_out;

    k_pool_bce<<<dim3(P, BN), 192>>>(logits, labels);
    k_cov<<<dim3(NPROB, NSTRIP), 96>>>();
    k_solve<<<NPROB, 32>>>(out);
}

// round 16
// speedup vs baseline: 1.1008x; 1.0235x over previous
#include <cuda_runtime.h>
#include <math.h>

typedef unsigned long long ull;

// Problem constants
static constexpr int BN = 4;            // batch
static constexpr int NC = 21;           // classes
static constexpr int H  = 512;
static constexpr int W  = 512;
static constexpr int P  = 171;          // pooled H/W
static constexpr int NH = 169;          // cropped size P - (radius-1)
static constexpr int NPROB = BN * NC;   // 84
static constexpr int MM = NH * NH;      // 28561
static constexpr double D_ALPHA = 5e-4;
static constexpr float  CLIP_MIN = 1e-6f;
static constexpr float  NEG_BIG  = -1e30f;
static constexpr int SPITCH = 172;      // smem pitch (floats, mult of 4)
static constexpr int SH = 16;           // strip height for k_cov
static constexpr int NSTRIP = (NH + SH - 1) / SH;  // 11
static constexpr int NBLK = P * BN;     // 684 pool blocks

// Scratch (static device globals: no allocation allowed)
__device__ float  g_la[NPROB * P * P];      // pooled one-hot labels
__device__ float  g_pr[NPROB * P * P];      // pooled probs
__device__ double g_S[NPROB * 18 * 18];     // raw second-moment Gram
__device__ double g_sums[NPROB * 18];       // raw first moments
__device__ float2 g_part[NBLK];             // per-block (bce, valid) - plain stores
__device__ double g_rmi[NPROB];
__device__ unsigned int g_ctr;              // last-block ticket (self-resetting)

// stream-pair-block map: 6 lower-tri pairs of the 3 stream-groups
__constant__ int c_PBI[6] = {0, 1, 1, 2, 2, 2};
__constant__ int c_PBJ[6] = {0, 0, 1, 0, 1, 2};

// ---------------------------------------------------------------------------
// Fused: BCE partials + sigmoid + one-hot + 3x3/s3/p1 maxpool.
// R15 pipeline; sbias smem REMOVED (biases derived from slab at the 8 staging
// positions only) -> 19KB smem/block -> more resident blocks to hide latency.
__global__ void __launch_bounds__(192, 6) k_pool_bce(const float* __restrict__ logits,
                                                     const int*   __restrict__ labels) {
    int py = blockIdx.x;        // 0..170
    int n  = blockIdx.y;        // 0..3
    int tid = threadIdx.x;
    int bid = n * P + py;

    // zero scratch consumed by k_cov (684 blocks x 42 = 28728 doubles exact)
    if (tid < 42) {
        int zi = bid * 42 + tid;
        if (zi < NPROB * 324) g_S[zi] = 0.0;
        else                  g_sums[zi - NPROB * 324] = 0.0;
    }

    __shared__ __align__(16) float slog[2][3][520];   // double-buffered, data at 4..515
    __shared__ int   slab[3][520];
    __shared__ float warp_b[6], warp_v[6];

    int y0 = py * 3 - 1;
    const int* lb = labels + (long)n * H * W;

    // stage labels (pads get l=NC -> mask 0)
    for (int i = tid; i < 3 * 520; i += 192) {
        int r = i / 520, x = i - r * 520;
        int xx = x - 4;
        int y  = y0 + r;
        bool v = ((unsigned)y < (unsigned)H) && ((unsigned)xx < (unsigned)W);
        slab[r][x] = v ? lb[y * W + xx] : NC;
    }
    // preset pad columns of BOTH logit buffers to -1e30 (never re-written)
    if (tid < 48) {
        int b = tid / 24, rem = tid - b * 24;
        int r = rem / 8, j = rem - r * 8;
        int x = (j < 4) ? j : 512 + j;
        slog[b][r][x] = NEG_BIG;
    }

    // fixed per-thread staging slots: i0 = tid, i1 = tid + 192
    int r0 = tid >> 7,         j0 = tid & 127;          // r0 in {0,1}
    int r1 = (tid + 192) >> 7, j1 = (tid + 192) & 127;  // r1 in {1,2}
    bool v0ok = (unsigned)(y0 + r0) < (unsigned)H;
    bool v1ok = (unsigned)(y0 + r1) < (unsigned)H;
    const long HW = (long)H * W;
    const float4* p0 = (const float4*)(logits + (long)(n * NC) * HW + (long)(y0 + r0) * W) + j0;
    const float4* p1 = (const float4*)(logits + (long)(n * NC) * HW + (long)(y0 + r1) * W) + j1;
    const long HW4 = HW / 4;

    // preload class 0 (bias applied after sync, once slab is ready)
    float4 a0 = make_float4(NEG_BIG, NEG_BIG, NEG_BIG, NEG_BIG), b0 = a0;
    if (v0ok) a0 = *p0;
    if (v1ok) b0 = *p1;
    p0 += HW4; p1 += HW4;
    __syncthreads();

    // loop-invariant staging biases derived from slab (registers)
    float4 bs0, bs1;
    {
        int base0 = 4 + 4 * j0, base1 = 4 + 4 * j1;
        bs0.x = (slab[r0][base0 + 0] < NC) ? 0.f : NEG_BIG;
        bs0.y = (slab[r0][base0 + 1] < NC) ? 0.f : NEG_BIG;
        bs0.z = (slab[r0][base0 + 2] < NC) ? 0.f : NEG_BIG;
        bs0.w = (slab[r0][base0 + 3] < NC) ? 0.f : NEG_BIG;
        bs1.x = (slab[r1][base1 + 0] < NC) ? 0.f : NEG_BIG;
        bs1.y = (slab[r1][base1 + 1] < NC) ? 0.f : NEG_BIG;
        bs1.z = (slab[r1][base1 + 2] < NC) ? 0.f : NEG_BIG;
        bs1.w = (slab[r1][base1 + 3] < NC) ? 0.f : NEG_BIG;
    }
    a0.x += bs0.x; a0.y += bs0.y; a0.z += bs0.z; a0.w += bs0.w;
    b0.x += bs1.x; b0.y += bs1.y; b0.z += bs1.z; b0.w += bs1.w;
    *(float4*)&slog[0][r0][4 + 4 * j0] = a0;
    *(float4*)&slog[0][r1][4 + 4 * j1] = b0;

    int  px  = tid;
    bool act = px < P;
    int  xb  = 3 * px + 3;
    int lab[9];
    unsigned wmask = 0u;
    float valid_part = 0.f, bce_part = 0.f;
    if (act) {
#pragma unroll
        for (int k = 0; k < 9; k++) {
            int r = k / 3, dx = k % 3;
            int l = slab[r][xb + dx];
            lab[k] = l;
            if (l < NC) { wmask |= 1u << l; valid_part += 1.f; }
        }
    }
    __syncthreads();

    const long PPP = (long)P * P;
    float* pla = g_la + (long)(n * NC) * PPP + (long)py * P + px;
    float* ppr = g_pr + (long)(n * NC) * PPP + (long)py * P + px;

    for (int c = 0; c < NC; c++) {
        // issue next class's loads early (latency hidden under compute)
        float4 na = make_float4(NEG_BIG, NEG_BIG, NEG_BIG, NEG_BIG), nb = na;
        if (c + 1 < NC) {
            if (v0ok) na = *p0;
            if (v1ok) nb = *p1;
            p0 += HW4; p1 += HW4;
        }
        if (act) {
            const float* sl = &slog[c & 1][0][xb];
            float mv = NEG_BIG, lin = 0.f, xs = 0.f, prod = 1.f;
#pragma unroll
            for (int k = 0; k < 9; k++) {
                int r = k / 3, dx = k % 3;
                float xv = sl[r * 520 + dx];
                mv   = fmaxf(mv, xv);
                lin += fmaxf(xv, 0.f);                 // masked: 0
                if (lab[k] == c) xs += xv;             // lab==c implies valid
                float e = __expf(-fabsf(xv));          // masked: 0
                prod *= (1.f + e);                     // masked: x1
            }
            bce_part += lin - xs + __logf(prod);       // ONE log per window
            float em  = __expf(-fabsf(mv));
            float rc  = __fdividef(1.f, 1.f + em);
            float sig = (mv >= 0.f) ? rc : em * rc;    // mv=-1e30 -> 0
            *pla = (float)((wmask >> c) & 1u);
            *ppr = sig + CLIP_MIN;
        }
        pla += PPP; ppr += PPP;
        if (c + 1 < NC) {   // biased STS after compute (waits on LDG here)
            na.x += bs0.x; na.y += bs0.y; na.z += bs0.z; na.w += bs0.w;
            nb.x += bs1.x; nb.y += bs1.y; nb.z += bs1.z; nb.w += bs1.w;
            *(float4*)&slog[(c + 1) & 1][r0][4 + 4 * j0] = na;
            *(float4*)&slog[(c + 1) & 1][r1][4 + 4 * j1] = nb;
        }
        __syncthreads();
    }

#pragma unroll
    for (int off = 16; off > 0; off >>= 1) {
        bce_part   += __shfl_down_sync(0xffffffffu, bce_part,   off);
        valid_part += __shfl_down_sync(0xffffffffu, valid_part, off);
    }
    int wid = tid >> 5, lane = tid & 31;
    if (lane == 0) { warp_b[wid] = bce_part; warp_v[wid] = valid_part; }
    __syncthreads();
    if (tid == 0) {
        float b = 0.f, v = 0.f;
#pragma unroll
        for (int w = 0; w < 6; w++) { b += warp_b[w]; v += warp_v[w]; }
        g_part[bid] = make_float2(b, v);
    }
}

// ---------------------------------------------------------------------------
// f32x2 helpers
__device__ __forceinline__ ull pk2(float lo, float hi) {
    ull r; asm("mov.b64 %0, {%1, %2};" : "=l"(r) : "f"(lo), "f"(hi)); return r;
}
#define FMA2(d, a, b) asm("fma.rn.f32x2 %0, %1, %2, %0;" : "+l"(d) : "l"(a), "l"(b))

// One step: acc[j*9+l*3+m] += PA[l-pos] * dup(Bj[m-pos])
#define DOSTEP(PL0, PL1, PL2, B00, B01, B02, B10, B11, B12) do {              \
    ull d00 = pk2((B00),(B00)), d01 = pk2((B01),(B01)), d02 = pk2((B02),(B02)); \
    ull d10 = pk2((B10),(B10)), d11 = pk2((B11),(B11)), d12 = pk2((B12),(B12)); \
    FMA2(acc[0],  PL0, d00); FMA2(acc[1],  PL0, d01); FMA2(acc[2],  PL0, d02); \
    FMA2(acc[3],  PL1, d00); FMA2(acc[4],  PL1, d01); FMA2(acc[5],  PL1, d02); \
    FMA2(acc[6],  PL2, d00); FMA2(acc[7],  PL2, d01); FMA2(acc[8],  PL2, d02); \
    FMA2(acc[9],  PL0, d10); FMA2(acc[10], PL0, d11); FMA2(acc[11], PL0, d12); \
    FMA2(acc[12], PL1, d10); FMA2(acc[13], PL1, d11); FMA2(acc[14], PL1, d12); \
    FMA2(acc[15], PL2, d10); FMA2(acc[16], PL2, d11); FMA2(acc[17], PL2, d12); \
} while (0)

#define PAW(t) ((t) < 4 ? PA[(t)]  : PAn[(t) - 4])
#define B0W(t) ((t) < 4 ? b0c[(t)] : b0n[(t) - 4])
#define B1W(t) ((t) < 4 ? b1c[(t)] : b1n[(t) - 4])

// Gram matrix of the 18 shifted views via 6 stream-pair-blocks; also folds in
// the per-view first-moment sums (row-total minus edges trick). (R15-exact)
__global__ void __launch_bounds__(96, 6) k_cov() {
    int p     = blockIdx.x;
    int strip = blockIdx.y;
    int ys = strip * SH;
    int sh = min(SH, NH - ys);

    __shared__ __align__(16) float sbuf[2 * 18 * SPITCH];  // la rows | pr rows
    __shared__ float srs[36];
    float* sla = sbuf;
    float* spr = sbuf + 18 * SPITCH;

    int tid = threadIdx.x;
    int row = tid & 15;
    int pb  = tid >> 4;
    const float* la = g_la + p * P * P;
    const float* pr = g_pr + p * P * P;

    int nrows = sh + 2;
    for (int i = tid; i < nrows * P; i += 96) {
        int r = i / P, x = i - r * P;
        sla[r * SPITCH + x] = la[(ys + r) * P + x];
        spr[r * SPITCH + x] = pr[(ys + r) * P + x];
    }
    __syncthreads();

    ull acc[18];
#pragma unroll
    for (int k = 0; k < 18; k++) acc[k] = 0ULL;

    if (row < sh) {
        int gi = c_PBI[pb], gj = c_PBJ[pb];
        int sA0 = 2 * gi, sA1 = 2 * gi + 1, sB0 = 2 * gj, sB1 = 2 * gj + 1;
        const float* pA0 = ((sA0 < 3) ? sla : spr) + ((sA0 < 3 ? sA0 : sA0 - 3) + row) * SPITCH;
        const float* pA1 = ((sA1 < 3) ? sla : spr) + ((sA1 < 3 ? sA1 : sA1 - 3) + row) * SPITCH;
        const float* pB0 = ((sB0 < 3) ? sla : spr) + ((sB0 < 3 ? sB0 : sB0 - 3) + row) * SPITCH;
        const float* pB1 = ((sB1 < 3) ? sla : spr) + ((sB1 < 3 ? sB1 : sB1 - 3) + row) * SPITCH;

        float4 va = *(const float4*)(pA0);
        float4 vb = *(const float4*)(pA1);
        ull PA[4] = { pk2(va.x, vb.x), pk2(va.y, vb.y), pk2(va.z, vb.z), pk2(va.w, vb.w) };
        float4 v0 = *(const float4*)(pB0);
        float4 v1 = *(const float4*)(pB1);
        float b0c[4] = { v0.x, v0.y, v0.z, v0.w };
        float b1c[4] = { v1.x, v1.y, v1.z, v1.w };

        for (int x = 0; x + 4 <= NH - 1; x += 4) {   // steps 0..167
            va = *(const float4*)(pA0 + x + 4);
            vb = *(const float4*)(pA1 + x + 4);
            ull PAn[4] = { pk2(va.x, vb.x), pk2(va.y, vb.y), pk2(va.z, vb.z), pk2(va.w, vb.w) };
            v0 = *(const float4*)(pB0 + x + 4);
            v1 = *(const float4*)(pB1 + x + 4);
            float b0n[4] = { v0.x, v0.y, v0.z, v0.w };
            float b1n[4] = { v1.x, v1.y, v1.z, v1.w };
#pragma unroll
            for (int s = 0; s < 4; s++)
                DOSTEP(PAW(s), PAW(s + 1), PAW(s + 2),
                       B0W(s), B0W(s + 1), B0W(s + 2),
                       B1W(s), B1W(s + 1), B1W(s + 2));
#pragma unroll
            for (int t = 0; t < 4; t++) { PA[t] = PAn[t]; b0c[t] = b0n[t]; b1c[t] = b1n[t]; }
        }
        DOSTEP(PA[0], PA[1], PA[2], b0c[0], b0c[1], b0c[2], b1c[0], b1c[1], b1c[2]);
    }

    // ---- folded first-moment sums (row totals minus edge elements) ----
    if (tid < 36) {
        int mp = tid / 18, r = tid % 18;
        float T = 0.f;
        if (r < sh + 2) {
            const float* rowp = (mp ? spr : sla) + r * SPITCH;
            for (int x = 0; x < P; x++) T += rowp[x];
        }
        srs[tid] = T;
    }
    __syncthreads();
    if (tid < 18) {
        int mp = tid / 9, dd = tid % 9, dy = dd / 3, dx = dd % 3;
        const float* base = mp ? spr : sla;
        float part = 0.f;
        for (int yl = 0; yl < sh; yl++) {
            int r = yl + dy;
            const float* rowp = base + r * SPITCH;
            float T = srs[mp * 18 + r];
            float rs = (dx == 0) ? T - rowp[169] - rowp[170]
                     : (dx == 1) ? T - rowp[0]   - rowp[170]
                     :             T - rowp[0]   - rowp[1];
            part += rs;
        }
        atomicAdd(&g_sums[p * 18 + tid], (double)part);
    }
    __syncthreads();

    // ---- reduce 96x36 partials over the 16 rows, flush to g_S ----
    float* red = sbuf;             // overlay (96*36 floats)
#pragma unroll
    for (int k = 0; k < 18; k++) {
        float lo, hi;
        asm("mov.b64 {%0, %1}, %2;" : "=f"(lo), "=f"(hi) : "l"(acc[k]));
        red[tid * 36 + k]      = lo;   // i = 0 (stream 2gi)
        red[tid * 36 + 18 + k] = hi;   // i = 1 (stream 2gi+1)
    }
    __syncthreads();
    for (int o = tid; o < 216; o += 96) {
        int pb2 = o / 36, q = o % 36;
        float ssum = 0.f;
#pragma unroll
        for (int r2 = 0; r2 < 16; r2++) ssum += red[(pb2 * 16 + r2) * 36 + q];
        int i = q / 18, k = q % 18;
        int j = k / 9, l = (k % 9) / 3, m = k % 3;
        int a = (2 * c_PBI[pb2] + i) * 3 + l;
        int b = (2 * c_PBJ[pb2] + j) * 3 + m;
        atomicAdd(&g_S[p * 324 + a * 18 + b], (double)ssum);
    }
}

// ---------------------------------------------------------------------------
// Register/shuffle 9x9 Cholesky (R15-exact): lane i (i<9) holds row i in
// a[0..8]; cross-lane via __shfl_sync with compile-time lane ids.
__device__ __forceinline__ float chol9_reg(float (&a)[9], int lane, bool want_log) {
    float ls = 0.f;
#pragma unroll
    for (int k = 0; k < 9; k++) {
        float dk = __shfl_sync(0xffffffffu, a[k], k);
        float d  = sqrtf(dk);
        if (want_log) ls += logf(d);
        float rd = __fdividef(1.f, d);
        if (lane == k) a[k] = d;
        else           a[k] *= rd;
#pragma unroll
        for (int j = k + 1; j < 9; j++) {
            float ljk = __shfl_sync(0xffffffffu, a[k], j);   // L[j][k]
            a[j] = fmaf(-a[k], ljk, a[j]);
        }
    }
    return ls;
}

// One warp per (n,c): assemble covariances in double, all-register shuffle
// solve (R15-exact). Last-finishing block does the final reduction.
__global__ void __launch_bounds__(32) k_solve(float* __restrict__ out) {
    int p    = blockIdx.x;
    int lane = threadIdx.x;
    __shared__ unsigned int ticket;
    const double* S  = g_S    + p * 324;
    const double* sm = g_sums + p * 18;
    const double invM = 1.0 / (double)MM;

    float pa[9];    // row lane of pr_cov+aI  -> L after chol
    float rhs[9];   // rhs[e] = la_pr_cov[lane][e]
    float lc[9];    // row lane of la_cov
    if (lane < 9) {
        int i = lane;
        double smi  = sm[i];
        double smpi = sm[9 + i];
#pragma unroll
        for (int j = 0; j < 9; j++) {
            double smj  = sm[j];
            double smpj = sm[9 + j];
            int a = 9 + i, b = 9 + j;
            int hi = a > b ? a : b, lo = a > b ? b : a;
            pa[j] = (float)(S[hi * 18 + lo] - smpi * smpj * invM + (i == j ? D_ALPHA : 0.0));
            rhs[j] = (float)(S[(9 + j) * 18 + i] - smi * smpj * invM);
            hi = i > j ? i : j; lo = i > j ? j : i;
            lc[j] = (float)(S[hi * 18 + lo] - smi * smj * invM);
        }
    } else {
#pragma unroll
        for (int j = 0; j < 9; j++) { pa[j] = 1.f; rhs[j] = 0.f; lc[j] = 0.f; }
    }

    chol9_reg(pa, lane, false);

    // Forward solve L V = la_pr_cov^T: lane d holds V column d in v[e]
    float v[9];
#pragma unroll
    for (int e = 0; e < 9; e++) {
        float t = rhs[e];
#pragma unroll
        for (int j = 0; j < e; j++) {
            float lej = __shfl_sync(0xffffffffu, pa[j], e);
            t = fmaf(-lej, v[j], t);
        }
        float lee = __shfl_sync(0xffffffffu, pa[e], e);
        v[e] = t * __fdividef(1.f, lee);
    }

    // appro_var row lane
    float av[9];
#pragma unroll
    for (int j = 0; j < 9; j++) {
        float t = lc[j];
#pragma unroll
        for (int k = 0; k < 9; k++) {
            float vkj = __shfl_sync(0xffffffffu, v[k], j);
            t = fmaf(-v[k], vkj, t);
        }
        if (lane == j) t += (float)D_ALPHA;
        av[j] = t;
    }

    float lsum = chol9_reg(av, lane, true);
    if (lane == 0) g_rmi[p] = (double)lsum;

    // ---- last-block final reduction (threadFenceReduction pattern) ----
    __threadfence();
    if (lane == 0) ticket = atomicAdd(&g_ctr, 1u);
    __syncwarp();
    if (ticket == NPROB - 1) {
        double rs = 0.0, bs = 0.0, vs = 0.0;
        for (int i = lane; i < NPROB; i += 32) rs += __ldcg(&g_rmi[i]);
        for (int i = lane; i < NBLK; i += 32) {
            float2 pv = __ldcg(&g_part[i]);
            bs += (double)pv.x; vs += (double)pv.y;
        }
#pragma unroll
        for (int off = 16; off > 0; off >>= 1) {
            rs += __shfl_down_sync(0xffffffffu, rs, off);
            bs += __shfl_down_sync(0xffffffffu, bs, off);
            vs += __shfl_down_sync(0xffffffffu, vs, off);
        }
        if (lane == 0) {
            double rmi = rs / 36.0;                 // mean over batch(4)/half_d(9)
            double bce = bs / (vs + 1.0);
            out[0] = (float)(0.5 * bce + 0.5 * rmi);
            g_ctr = 0;                              // reset for next graph replay
        }
    }
}

// ---------------------------------------------------------------------------
extern "C" void kernel_launch(void* const* d_in, const int* in_sizes, int n_in,
                              void* d_out, int out_size) {
    const float* logits = (const float*)d_in[0];
    const int*   labels = (const int*)d_in[1];
    float* out = (float*)d_out;

    k_pool_bce<<<dim3(P, BN), 192>>>(logits, labels);
    k_cov<<<dim3(NPROB, NSTRIP), 96>>>();
    k_solve<<<NPROB, 32>>>(out);
}

// round 17
// speedup vs baseline: 1.1238x; 1.0209x over previous
#include <cuda_runtime.h>
#include <math.h>

typedef unsigned long long ull;

// Problem constants
static constexpr int BN = 4;            // batch
static constexpr int NC = 21;           // classes
static constexpr int H  = 512;
static constexpr int W  = 512;
static constexpr int P  = 171;          // pooled H/W
static constexpr int NH = 169;          // cropped size P - (radius-1)
static constexpr int NPROB = BN * NC;   // 84
static constexpr int MM = NH * NH;      // 28561
static constexpr double D_ALPHA = 5e-4;
static constexpr float  CLIP_MIN = 1e-6f;
static constexpr float  NEG_BIG  = -1e30f;
static constexpr int SPITCH = 172;      // smem pitch (floats, mult of 4)
static constexpr int SH = 16;           // strip height for k_cov
static constexpr int NSTRIP = (NH + SH - 1) / SH;  // 11
static constexpr int NBLK = P * BN;     // 684 pool blocks

// Scratch (static device globals: no allocation allowed)
__device__ float  g_la[NPROB * P * P];      // pooled one-hot labels
__device__ float  g_pr[NPROB * P * P];      // pooled probs
__device__ double g_S[NPROB * 18 * 18];     // raw second-moment Gram
__device__ double g_sums[NPROB * 18];       // raw first moments
__device__ float2 g_part[NBLK];             // per-block (bce, valid) - plain stores
__device__ double g_rmi[NPROB];
__device__ unsigned int g_ctr;              // last-block ticket (self-resetting)

// stream-pair-block map: 6 lower-tri pairs of the 3 stream-groups
__constant__ int c_PBI[6] = {0, 1, 1, 2, 2, 2};
__constant__ int c_PBJ[6] = {0, 0, 1, 0, 1, 2};

// ---------------------------------------------------------------------------
// Fused: BCE partials + sigmoid + one-hot + 3x3/s3/p1 maxpool (R16-exact).
__global__ void __launch_bounds__(192, 6) k_pool_bce(const float* __restrict__ logits,
                                                     const int*   __restrict__ labels) {
    int py = blockIdx.x;        // 0..170
    int n  = blockIdx.y;        // 0..3
    int tid = threadIdx.x;
    int bid = n * P + py;

    // zero scratch consumed by k_cov (684 blocks x 42 = 28728 doubles exact)
    if (tid < 42) {
        int zi = bid * 42 + tid;
        if (zi < NPROB * 324) g_S[zi] = 0.0;
        else                  g_sums[zi - NPROB * 324] = 0.0;
    }

    __shared__ __align__(16) float slog[2][3][520];   // double-buffered, data at 4..515
    __shared__ int   slab[3][520];
    __shared__ float warp_b[6], warp_v[6];

    int y0 = py * 3 - 1;
    const int* lb = labels + (long)n * H * W;

    // stage labels (pads get l=NC -> mask 0)
    for (int i = tid; i < 3 * 520; i += 192) {
        int r = i / 520, x = i - r * 520;
        int xx = x - 4;
        int y  = y0 + r;
        bool v = ((unsigned)y < (unsigned)H) && ((unsigned)xx < (unsigned)W);
        slab[r][x] = v ? lb[y * W + xx] : NC;
    }
    // preset pad columns of BOTH logit buffers to -1e30 (never re-written)
    if (tid < 48) {
        int b = tid / 24, rem = tid - b * 24;
        int r = rem / 8, j = rem - r * 8;
        int x = (j < 4) ? j : 512 + j;
        slog[b][r][x] = NEG_BIG;
    }

    // fixed per-thread staging slots: i0 = tid, i1 = tid + 192
    int r0 = tid >> 7,         j0 = tid & 127;          // r0 in {0,1}
    int r1 = (tid + 192) >> 7, j1 = (tid + 192) & 127;  // r1 in {1,2}
    bool v0ok = (unsigned)(y0 + r0) < (unsigned)H;
    bool v1ok = (unsigned)(y0 + r1) < (unsigned)H;
    const long HW = (long)H * W;
    const float4* p0 = (const float4*)(logits + (long)(n * NC) * HW + (long)(y0 + r0) * W) + j0;
    const float4* p1 = (const float4*)(logits + (long)(n * NC) * HW + (long)(y0 + r1) * W) + j1;
    const long HW4 = HW / 4;

    // preload class 0 (bias applied after sync, once slab is ready)
    float4 a0 = make_float4(NEG_BIG, NEG_BIG, NEG_BIG, NEG_BIG), b0 = a0;
    if (v0ok) a0 = *p0;
    if (v1ok) b0 = *p1;
    p0 += HW4; p1 += HW4;
    __syncthreads();

    // loop-invariant staging biases derived from slab (registers)
    float4 bs0, bs1;
    {
        int base0 = 4 + 4 * j0, base1 = 4 + 4 * j1;
        bs0.x = (slab[r0][base0 + 0] < NC) ? 0.f : NEG_BIG;
        bs0.y = (slab[r0][base0 + 1] < NC) ? 0.f : NEG_BIG;
        bs0.z = (slab[r0][base0 + 2] < NC) ? 0.f : NEG_BIG;
        bs0.w = (slab[r0][base0 + 3] < NC) ? 0.f : NEG_BIG;
        bs1.x = (slab[r1][base1 + 0] < NC) ? 0.f : NEG_BIG;
        bs1.y = (slab[r1][base1 + 1] < NC) ? 0.f : NEG_BIG;
        bs1.z = (slab[r1][base1 + 2] < NC) ? 0.f : NEG_BIG;
        bs1.w = (slab[r1][base1 + 3] < NC) ? 0.f : NEG_BIG;
    }
    a0.x += bs0.x; a0.y += bs0.y; a0.z += bs0.z; a0.w += bs0.w;
    b0.x += bs1.x; b0.y += bs1.y; b0.z += bs1.z; b0.w += bs1.w;
    *(float4*)&slog[0][r0][4 + 4 * j0] = a0;
    *(float4*)&slog[0][r1][4 + 4 * j1] = b0;

    int  px  = tid;
    bool act = px < P;
    int  xb  = 3 * px + 3;
    int lab[9];
    unsigned wmask = 0u;
    float valid_part = 0.f, bce_part = 0.f;
    if (act) {
#pragma unroll
        for (int k = 0; k < 9; k++) {
            int r = k / 3, dx = k % 3;
            int l = slab[r][xb + dx];
            lab[k] = l;
            if (l < NC) { wmask |= 1u << l; valid_part += 1.f; }
        }
    }
    __syncthreads();

    const long PPP = (long)P * P;
    float* pla = g_la + (long)(n * NC) * PPP + (long)py * P + px;
    float* ppr = g_pr + (long)(n * NC) * PPP + (long)py * P + px;

    for (int c = 0; c < NC; c++) {
        // issue next class's loads early (latency hidden under compute)
        float4 na = make_float4(NEG_BIG, NEG_BIG, NEG_BIG, NEG_BIG), nb = na;
        if (c + 1 < NC) {
            if (v0ok) na = *p0;
            if (v1ok) nb = *p1;
            p0 += HW4; p1 += HW4;
        }
        if (act) {
            const float* sl = &slog[c & 1][0][xb];
            float mv = NEG_BIG, lin = 0.f, xs = 0.f, prod = 1.f;
#pragma unroll
            for (int k = 0; k < 9; k++) {
                int r = k / 3, dx = k % 3;
                float xv = sl[r * 520 + dx];
                mv   = fmaxf(mv, xv);
                lin += fmaxf(xv, 0.f);                 // masked: 0
                if (lab[k] == c) xs += xv;             // lab==c implies valid
                float e = __expf(-fabsf(xv));          // masked: 0
                prod *= (1.f + e);                     // masked: x1
            }
            bce_part += lin - xs + __logf(prod);       // ONE log per window
            float em  = __expf(-fabsf(mv));
            float rc  = __fdividef(1.f, 1.f + em);
            float sig = (mv >= 0.f) ? rc : em * rc;    // mv=-1e30 -> 0
            *pla = (float)((wmask >> c) & 1u);
            *ppr = sig + CLIP_MIN;
        }
        pla += PPP; ppr += PPP;
        if (c + 1 < NC) {   // biased STS after compute (waits on LDG here)
            na.x += bs0.x; na.y += bs0.y; na.z += bs0.z; na.w += bs0.w;
            nb.x += bs1.x; nb.y += bs1.y; nb.z += bs1.z; nb.w += bs1.w;
            *(float4*)&slog[(c + 1) & 1][r0][4 + 4 * j0] = na;
            *(float4*)&slog[(c + 1) & 1][r1][4 + 4 * j1] = nb;
        }
        __syncthreads();
    }

#pragma unroll
    for (int off = 16; off > 0; off >>= 1) {
        bce_part   += __shfl_down_sync(0xffffffffu, bce_part,   off);
        valid_part += __shfl_down_sync(0xffffffffu, valid_part, off);
    }
    int wid = tid >> 5, lane = tid & 31;
    if (lane == 0) { warp_b[wid] = bce_part; warp_v[wid] = valid_part; }
    __syncthreads();
    if (tid == 0) {
        float b = 0.f, v = 0.f;
#pragma unroll
        for (int w = 0; w < 6; w++) { b += warp_b[w]; v += warp_v[w]; }
        g_part[bid] = make_float2(b, v);
    }
}

// ---------------------------------------------------------------------------
// f32x2 helpers
__device__ __forceinline__ ull pk2(float lo, float hi) {
    ull r; asm("mov.b64 %0, {%1, %2};" : "=l"(r) : "f"(lo), "f"(hi)); return r;
}
#define FMA2(d, a, b) asm("fma.rn.f32x2 %0, %1, %2, %0;" : "+l"(d) : "l"(a), "l"(b))

// One step: acc[j*9+l*3+m] += PA[l-pos] * dup(Bj[m-pos])
#define DOSTEP(PL0, PL1, PL2, B00, B01, B02, B10, B11, B12) do {              \
    ull d00 = pk2((B00),(B00)), d01 = pk2((B01),(B01)), d02 = pk2((B02),(B02)); \
    ull d10 = pk2((B10),(B10)), d11 = pk2((B11),(B11)), d12 = pk2((B12),(B12)); \
    FMA2(acc[0],  PL0, d00); FMA2(acc[1],  PL0, d01); FMA2(acc[2],  PL0, d02); \
    FMA2(acc[3],  PL1, d00); FMA2(acc[4],  PL1, d01); FMA2(acc[5],  PL1, d02); \
    FMA2(acc[6],  PL2, d00); FMA2(acc[7],  PL2, d01); FMA2(acc[8],  PL2, d02); \
    FMA2(acc[9],  PL0, d10); FMA2(acc[10], PL0, d11); FMA2(acc[11], PL0, d12); \
    FMA2(acc[12], PL1, d10); FMA2(acc[13], PL1, d11); FMA2(acc[14], PL1, d12); \
    FMA2(acc[15], PL2, d10); FMA2(acc[16], PL2, d11); FMA2(acc[17], PL2, d12); \
} while (0)

#define PAW(t) ((t) < 4 ? PA[(t)]  : PAn[(t) - 4])
#define B0W(t) ((t) < 4 ? b0c[(t)] : b0n[(t) - 4])
#define B1W(t) ((t) < 4 ? b1c[(t)] : b1n[(t) - 4])

// Gram matrix of the 18 shifted views via 6 stream-pair-blocks; also folds in
// the per-view first-moment sums. Residency raised 6->8 so the 924-block grid
// fits ONE wave (148*8=1184 slots; at 6 it was 888 -> a 36-block 2nd wave that
// nearly doubled the kernel).
__global__ void __launch_bounds__(96, 8) k_cov() {
    int p     = blockIdx.x;
    int strip = blockIdx.y;
    int ys = strip * SH;
    int sh = min(SH, NH - ys);

    __shared__ __align__(16) float sbuf[2 * 18 * SPITCH];  // la rows | pr rows
    __shared__ float srs[36];
    float* sla = sbuf;
    float* spr = sbuf + 18 * SPITCH;

    int tid = threadIdx.x;
    int row = tid & 15;
    int pb  = tid >> 4;
    const float* la = g_la + p * P * P;
    const float* pr = g_pr + p * P * P;

    int nrows = sh + 2;
    for (int i = tid; i < nrows * P; i += 96) {
        int r = i / P, x = i - r * P;
        sla[r * SPITCH + x] = la[(ys + r) * P + x];
        spr[r * SPITCH + x] = pr[(ys + r) * P + x];
    }
    __syncthreads();

    ull acc[18];
#pragma unroll
    for (int k = 0; k < 18; k++) acc[k] = 0ULL;

    if (row < sh) {
        int gi = c_PBI[pb], gj = c_PBJ[pb];
        int sA0 = 2 * gi, sA1 = 2 * gi + 1, sB0 = 2 * gj, sB1 = 2 * gj + 1;
        const float* pA0 = ((sA0 < 3) ? sla : spr) + ((sA0 < 3 ? sA0 : sA0 - 3) + row) * SPITCH;
        const float* pA1 = ((sA1 < 3) ? sla : spr) + ((sA1 < 3 ? sA1 : sA1 - 3) + row) * SPITCH;
        const float* pB0 = ((sB0 < 3) ? sla : spr) + ((sB0 < 3 ? sB0 : sB0 - 3) + row) * SPITCH;
        const float* pB1 = ((sB1 < 3) ? sla : spr) + ((sB1 < 3 ? sB1 : sB1 - 3) + row) * SPITCH;

        float4 va = *(const float4*)(pA0);
        float4 vb = *(const float4*)(pA1);
        ull PA[4] = { pk2(va.x, vb.x), pk2(va.y, vb.y), pk2(va.z, vb.z), pk2(va.w, vb.w) };
        float4 v0 = *(const float4*)(pB0);
        float4 v1 = *(const float4*)(pB1);
        float b0c[4] = { v0.x, v0.y, v0.z, v0.w };
        float b1c[4] = { v1.x, v1.y, v1.z, v1.w };

        for (int x = 0; x + 4 <= NH - 1; x += 4) {   // steps 0..167
            va = *(const float4*)(pA0 + x + 4);
            vb = *(const float4*)(pA1 + x + 4);
            ull PAn[4] = { pk2(va.x, vb.x), pk2(va.y, vb.y), pk2(va.z, vb.z), pk2(va.w, vb.w) };
            v0 = *(const float4*)(pB0 + x + 4);
            v1 = *(const float4*)(pB1 + x + 4);
            float b0n[4] = { v0.x, v0.y, v0.z, v0.w };
            float b1n[4] = { v1.x, v1.y, v1.z, v1.w };
#pragma unroll
            for (int s = 0; s < 4; s++)
                DOSTEP(PAW(s), PAW(s + 1), PAW(s + 2),
                       B0W(s), B0W(s + 1), B0W(s + 2),
                       B1W(s), B1W(s + 1), B1W(s + 2));
#pragma unroll
            for (int t = 0; t < 4; t++) { PA[t] = PAn[t]; b0c[t] = b0n[t]; b1c[t] = b1n[t]; }
        }
        DOSTEP(PA[0], PA[1], PA[2], b0c[0], b0c[1], b0c[2], b1c[0], b1c[1], b1c[2]);
    }

    // ---- folded first-moment sums (row totals minus edge elements) ----
    if (tid < 36) {
        int mp = tid / 18, r = tid % 18;
        float T = 0.f;
        if (r < sh + 2) {
            const float* rowp = (mp ? spr : sla) + r * SPITCH;
            for (int x = 0; x < P; x++) T += rowp[x];
        }
        srs[tid] = T;
    }
    __syncthreads();
    if (tid < 18) {
        int mp = tid / 9, dd = tid % 9, dy = dd / 3, dx = dd % 3;
        const float* base = mp ? spr : sla;
        float part = 0.f;
        for (int yl = 0; yl < sh; yl++) {
            int r = yl + dy;
            const float* rowp = base + r * SPITCH;
            float T = srs[mp * 18 + r];
            float rs = (dx == 0) ? T - rowp[169] - rowp[170]
                     : (dx == 1) ? T - rowp[0]   - rowp[170]
                     :             T - rowp[0]   - rowp[1];
            part += rs;
        }
        atomicAdd(&g_sums[p * 18 + tid], (double)part);
    }
    __syncthreads();

    // ---- reduce 96x36 partials over the 16 rows, flush to g_S ----
    float* red = sbuf;             // overlay (96*36 floats)
#pragma unroll
    for (int k = 0; k < 18; k++) {
        float lo, hi;
        asm("mov.b64 {%0, %1}, %2;" : "=f"(lo), "=f"(hi) : "l"(acc[k]));
        red[tid * 36 + k]      = lo;   // i = 0 (stream 2gi)
        red[tid * 36 + 18 + k] = hi;   // i = 1 (stream 2gi+1)
    }
    __syncthreads();
    for (int o = tid; o < 216; o += 96) {
        int pb2 = o / 36, q = o % 36;
        float ssum = 0.f;
#pragma unroll
        for (int r2 = 0; r2 < 16; r2++) ssum += red[(pb2 * 16 + r2) * 36 + q];
        int i = q / 18, k = q % 18;
        int j = k / 9, l = (k % 9) / 3, m = k % 3;
        int a = (2 * c_PBI[pb2] + i) * 3 + l;
        int b = (2 * c_PBJ[pb2] + j) * 3 + m;
        atomicAdd(&g_S[p * 324 + a * 18 + b], (double)ssum);
    }
}

// ---------------------------------------------------------------------------
// Register/shuffle 9x9 Cholesky (R15-exact): lane i (i<9) holds row i in
// a[0..8]; cross-lane via __shfl_sync with compile-time lane ids.
__device__ __forceinline__ float chol9_reg(float (&a)[9], int lane, bool want_log) {
    float ls = 0.f;
#pragma unroll
    for (int k = 0; k < 9; k++) {
        float dk = __shfl_sync(0xffffffffu, a[k], k);
        float d  = sqrtf(dk);
        if (want_log) ls += logf(d);
        float rd = __fdividef(1.f, d);
        if (lane == k) a[k] = d;
        else           a[k] *= rd;
#pragma unroll
        for (int j = k + 1; j < 9; j++) {
            float ljk = __shfl_sync(0xffffffffu, a[k], j);   // L[j][k]
            a[j] = fmaf(-a[k], ljk, a[j]);
        }
    }
    return ls;
}

// One warp per (n,c): assemble covariances in double, all-register shuffle
// solve (R15-exact). Last-finishing block does the final reduction.
__global__ void __launch_bounds__(32) k_solve(float* __restrict__ out) {
    int p    = blockIdx.x;
    int lane = threadIdx.x;
    __shared__ unsigned int ticket;
    const double* S  = g_S    + p * 324;
    const double* sm = g_sums + p * 18;
    const double invM = 1.0 / (double)MM;

    float pa[9];    // row lane of pr_cov+aI  -> L after chol
    float rhs[9];   // rhs[e] = la_pr_cov[lane][e]
    float lc[9];    // row lane of la_cov
    if (lane < 9) {
        int i = lane;
        double smi  = sm[i];
        double smpi = sm[9 + i];
#pragma unroll
        for (int j = 0; j < 9; j++) {
            double smj  = sm[j];
            double smpj = sm[9 + j];
            int a = 9 + i, b = 9 + j;
            int hi = a > b ? a : b, lo = a > b ? b : a;
            pa[j] = (float)(S[hi * 18 + lo] - smpi * smpj * invM + (i == j ? D_ALPHA : 0.0));
            rhs[j] = (float)(S[(9 + j) * 18 + i] - smi * smpj * invM);
            hi = i > j ? i : j; lo = i > j ? j : i;
            lc[j] = (float)(S[hi * 18 + lo] - smi * smj * invM);
        }
    } else {
#pragma unroll
        for (int j = 0; j < 9; j++) { pa[j] = 1.f; rhs[j] = 0.f; lc[j] = 0.f; }
    }

    chol9_reg(pa, lane, false);

    // Forward solve L V = la_pr_cov^T: lane d holds V column d in v[e]
    float v[9];
#pragma unroll
    for (int e = 0; e < 9; e++) {
        float t = rhs[e];
#pragma unroll
        for (int j = 0; j < e; j++) {
            float lej = __shfl_sync(0xffffffffu, pa[j], e);
            t = fmaf(-lej, v[j], t);
        }
        float lee = __shfl_sync(0xffffffffu, pa[e], e);
        v[e] = t * __fdividef(1.f, lee);
    }

    // appro_var row lane
    float av[9];
#pragma unroll
    for (int j = 0; j < 9; j++) {
        float t = lc[j];
#pragma unroll
        for (int k = 0; k < 9; k++) {
            float vkj = __shfl_sync(0xffffffffu, v[k], j);
            t = fmaf(-v[k], vkj, t);
        }
        if (lane == j) t += (float)D_ALPHA;
        av[j] = t;
    }

    float lsum = chol9_reg(av, lane, true);
    if (lane == 0) g_rmi[p] = (double)lsum;

    // ---- last-block final reduction (threadFenceReduction pattern) ----
    __threadfence();
    if (lane == 0) ticket = atomicAdd(&g_ctr, 1u);
    __syncwarp();
    if (ticket == NPROB - 1) {
        double rs = 0.0, bs = 0.0, vs = 0.0;
        for (int i = lane; i < NPROB; i += 32) rs += __ldcg(&g_rmi[i]);
        for (int i = lane; i < NBLK; i += 32) {
            float2 pv = __ldcg(&g_part[i]);
            bs += (double)pv.x; vs += (double)pv.y;
        }
#pragma unroll
        for (int off = 16; off > 0; off >>= 1) {
            rs += __shfl_down_sync(0xffffffffu, rs, off);
            bs += __shfl_down_sync(0xffffffffu, bs, off);
            vs += __shfl_down_sync(0xffffffffu, vs, off);
        }
        if (lane == 0) {
            double rmi = rs / 36.0;                 // mean over batch(4)/half_d(9)
            double bce = bs / (vs + 1.0);
            out[0] = (float)(0.5 * bce + 0.5 * rmi);
            g_ctr = 0;                              // reset for next graph replay
        }
    }
}

// ---------------------------------------------------------------------------
extern "C" void kernel_launch(void* const* d_in, const int* in_sizes, int n_in,
                              void* d_out, int out_size) {
    const float* logits = (const float*)d_in[0];
    const int*   labels = (const int*)d_in[1];
    float* out = (float*)d_out;

    k_pool_bce<<<dim3(P, BN), 192>>>(logits, labels);
    k_cov<<<dim3(NPROB, NSTRIP), 96>>>();
    k_solve<<<NPROB, 32>>>(out);
}